// round 12
// baseline (speedup 1.0000x reference)
#include <cuda_runtime.h>
#include <cstdint>
#include <math.h>

#define NB 2
#define NC 64
#define NN 144
#define NM 145
#define NL 800
#define NMP 148   // padded alphaT row stride (float4-aligned)

// ---------------- scratch (device globals; no allocation) -------------------
__device__ float g_pos[NB*NN*NC];
__device__ float g_pa[NL];
__device__ float g_nodes_cg[NB*NM*NC];
__device__ float g_nodes_id[NB*NM*NC];
__device__ float g_pi [NB*NN*NL];
__device__ float g_pjp[NB*NN*NL];
__device__ float g_xl_cg[NB*NM*NL];
__device__ float g_xr_cg[NB*NM*NL];
__device__ float g_xl_id[NB*NM*NL];
__device__ float g_xr_id[NB*NM*NL];
__device__ float g_gumT[NB*NN*NN];        // gumbel0-gumbel1, TRANSPOSED [b][j][i]
__device__ float g_alphaT[NB*NM*NMP];
__device__ float g_agg_cg[NB*NM*NL];
__device__ float g_agg_id[NB*NM*NL];
__device__ float g_zp[10*2*192*192];      // disc |.| partials, [chunk][b][j][i]
__device__ float g_zg[10*2*192*192];      // gat  |.| partials, [chunk][b][j][i]
__device__ float g_ud[NB*NN], g_vd[NB*NN];
__device__ float g_ug[NB*NM], g_vg[NB*NM];
__device__ float g_loss1, g_loss2;

// ---------------- threefry2x32 (JAX-exact, partitionable) -------------------
__host__ __device__ __forceinline__ void tf2x32(uint32_t k0, uint32_t k1,
                                                uint32_t x0, uint32_t x1,
                                                uint32_t &o0, uint32_t &o1) {
  uint32_t k2 = k0 ^ k1 ^ 0x1BD11BDAu;
  x0 += k0; x1 += k1;
#define TFR(r) { x0 += x1; x1 = (x1 << (r)) | (x1 >> (32 - (r))); x1 ^= x0; }
  TFR(13) TFR(15) TFR(26) TFR(6)
  x0 += k1; x1 += k2 + 1u;
  TFR(17) TFR(29) TFR(16) TFR(24)
  x0 += k2; x1 += k0 + 2u;
  TFR(13) TFR(15) TFR(26) TFR(6)
  x0 += k0; x1 += k1 + 3u;
  TFR(17) TFR(29) TFR(16) TFR(24)
  x0 += k1; x1 += k2 + 4u;
  TFR(13) TFR(15) TFR(26) TFR(6)
  x0 += k2; x1 += k0 + 5u;
#undef TFR
  o0 = x0; o1 = x1;
}

__device__ __forceinline__ uint32_t jx_bits(uint32_t k0, uint32_t k1, uint32_t f) {
  uint32_t o0, o1; tf2x32(k0, k1, 0u, f, o0, o1); return o0 ^ o1;
}
__device__ __forceinline__ float jx_u01(uint32_t bits) {
  return __uint_as_float((bits >> 9) | 0x3F800000u) - 1.0f;
}
__device__ __forceinline__ float jx_gumbel(uint32_t k0, uint32_t k1, uint32_t f) {
  float u01 = jx_u01(jx_bits(k0, k1, f));
  const float tiny = 1.17549435e-38f;
  float u = fmaxf(tiny, u01 + tiny);
  return -logf(-logf(u));
}
__device__ __forceinline__ float jx_normal(uint32_t k0, uint32_t k1, uint32_t f) {
  float u01 = jx_u01(jx_bits(k0, k1, f));
  const float lo = -0.99999994f;
  float u = fmaxf(lo, u01 * 2.0f + lo);
  return 1.41421356f * erfinvf(u);
}

// ---------------- K0: pos, pa, noisy nodes, gumbel diffs(T), zero u/v -------
__global__ void k0_prep(const float* __restrict__ latent,
                        const float* __restrict__ a_dense_b,
                        const float* __restrict__ disc_w1,
                        const float* __restrict__ disc_b1,
                        uint32_t kg0, uint32_t kg1,
                        uint32_t n10, uint32_t n11, uint32_t n20, uint32_t n21) {
  int tid = blockIdx.x * blockDim.x + threadIdx.x;
  if (tid == 0) { g_loss1 = 0.f; g_loss2 = 0.f; }
  const float t = -logf(10000.0f) / 64.0f;
  const int R0 = NB*NN*NC;
  const int R1 = R0 + NL;
  const int R2 = R1 + 2*NB*NM*NC;
  const int R3 = R2 + 2*NB*NN + 2*NB*NM;
  const int R4 = R3 + NB*NN*NN;
  if (tid < R0) {
    int b = tid / (NN*NC), r = tid % (NN*NC);
    int n = r >> 6, c = r & 63;
    int h = n / 12, w = n % 12;
    float lat = latent[((b*NC + c)*12 + h)*12 + w];
    float dv = expf((float)(2*(c >> 1)) * t);
    float ang = (float)n * dv;
    float pe = (c & 1) ? cosf(ang) : sinf(ang);
    g_pos[tid] = lat + pe;
  } else if (tid < R1) {
    int l = tid - R0;
    float s = disc_b1[l];
    #pragma unroll 8
    for (int c = 0; c < NC; c++) s += a_dense_b[c] * disc_w1[(2*NC + c)*NL + l];
    g_pa[l] = s;
  } else if (tid < R2) {
    int q = tid - R1;
    int which = q / (NB*NM*NC);
    int f = q % (NB*NM*NC);
    int b = f / (NM*NC), r = f % (NM*NC);
    int m = r >> 6, c = r & 63;
    float base;
    if (m < NN) {
      int h = m / 12, w = m % 12;
      float lat = latent[((b*NC + c)*12 + h)*12 + w];
      float dv = expf((float)(2*(c >> 1)) * t);
      float ang = (float)m * dv;
      float pe = (c & 1) ? cosf(ang) : sinf(ang);
      base = lat + pe;
    } else {
      base = a_dense_b[c];
    }
    uint32_t k0 = which ? n20 : n10, k1 = which ? n21 : n11;
    float noise = jx_normal(k0, k1, (uint32_t)f);
    (which ? g_nodes_id : g_nodes_cg)[f] = base + noise;
  } else if (tid < R3) {
    int q = tid - R2;
    if (q < NB*NN) g_ud[q] = 0.f;
    else if (q < 2*NB*NN) g_vd[q - NB*NN] = 0.f;
    else if (q < 2*NB*NN + NB*NM) g_ug[q - 2*NB*NN] = 0.f;
    else g_vg[q - 2*NB*NN - NB*NM] = 0.f;
  } else if (tid < R4) {
    int gidx = tid - R3;                 // (b*NN + i)*NN + j  (JAX sample order)
    int b = gidx / (NN*NN), r = gidx % (NN*NN);
    int i = r / NN, j = r % NN;
    uint32_t f = (uint32_t)(gidx * 2);
    float gg0 = jx_gumbel(kg0, kg1, f);
    float gg1 = jx_gumbel(kg0, kg1, f + 1u);
    g_gumT[(b*NN + j)*NN + i] = gg0 - gg1;   // transposed store
  }
}

// ---------------- K1: six (rows x 64)@(64 x 800) GEMMs, 64x64 tile, 4x4 -----
__global__ __launch_bounds__(256)
void k1_gemm64(const float* __restrict__ disc_w1,
               const float* __restrict__ gat_wl,
               const float* __restrict__ gat_wr,
               const float* __restrict__ gat_bl,
               const float* __restrict__ gat_br,
               const float* __restrict__ disc_w2,
               const float* __restrict__ gat_att) {
  __shared__ __align__(16) float Ast[64][68];   // [k][row]
  __shared__ __align__(16) float Ws[64][68];    // [k][col]
  const float *A, *W, *bias; float *C; int rows;
  const float *uvw = nullptr; float *uvdst = nullptr;
  switch (blockIdx.z) {
    case 0:  A = g_pos;      W = disc_w1;          bias = nullptr; C = g_pi;    rows = NB*NN;
             uvw = disc_w2; uvdst = g_ud; break;
    case 1:  A = g_pos;      W = disc_w1 + NC*NL;  bias = g_pa;    C = g_pjp;   rows = NB*NN;
             uvw = disc_w2; uvdst = g_vd; break;
    case 2:  A = g_nodes_cg; W = gat_wl;           bias = gat_bl;  C = g_xl_cg; rows = NB*NM;
             uvw = gat_att; uvdst = g_ug; break;
    case 3:  A = g_nodes_cg; W = gat_wr;           bias = gat_br;  C = g_xr_cg; rows = NB*NM;
             uvw = gat_att; uvdst = g_vg; break;
    case 4:  A = g_nodes_id; W = gat_wl;           bias = gat_bl;  C = g_xl_id; rows = NB*NM; break;
    default: A = g_nodes_id; W = gat_wr;           bias = gat_br;  C = g_xr_id; rows = NB*NM; break;
  }
  int r0 = blockIdx.x * 64, c0 = blockIdx.y * 64;
  if (r0 >= rows) return;
  int tid = threadIdx.x;
  int ty = tid >> 4, tx = tid & 15;
  int rr = tid >> 2, g = tid & 3;
  #pragma unroll
  for (int m = 0; m < 4; m++) {
    int k = g*16 + m*4;
    float4 av = make_float4(0.f, 0.f, 0.f, 0.f);
    if (r0 + rr < rows) av = *(const float4*)&A[(r0 + rr)*NC + k];
    Ast[k+0][rr] = av.x; Ast[k+1][rr] = av.y; Ast[k+2][rr] = av.z; Ast[k+3][rr] = av.w;
  }
  #pragma unroll
  for (int u = 0; u < 4; u++) {
    int idx = tid + u*256;
    int k = idx >> 4, c4 = (idx & 15) * 4;
    float4 wv = make_float4(0.f, 0.f, 0.f, 0.f);
    if (c0 + c4 < NL) wv = *(const float4*)&W[k*NL + c0 + c4];
    *(float4*)&Ws[k][c4] = wv;
  }
  __syncthreads();
  float acc[4][4] = {};
  #pragma unroll
  for (int k = 0; k < 64; k++) {
    float4 x = *(const float4*)&Ast[k][4*ty];
    float4 w = *(const float4*)&Ws[k][4*tx];
    float xv[4] = {x.x, x.y, x.z, x.w};
    float wv[4] = {w.x, w.y, w.z, w.w};
    #pragma unroll
    for (int di = 0; di < 4; di++)
      #pragma unroll
      for (int dj = 0; dj < 4; dj++)
        acc[di][dj] = fmaf(xv[di], wv[dj], acc[di][dj]);
  }
  float bb[4], v[4][4];
  #pragma unroll
  for (int dj = 0; dj < 4; dj++) {
    int c = c0 + 4*tx + dj;
    bb[dj] = (bias && c < NL) ? bias[c] : 0.f;
  }
  #pragma unroll
  for (int di = 0; di < 4; di++) {
    int r = r0 + 4*ty + di;
    #pragma unroll
    for (int dj = 0; dj < 4; dj++) v[di][dj] = acc[di][dj] + bb[dj];
    if (r < rows) {
      #pragma unroll
      for (int dj = 0; dj < 4; dj++) {
        int c = c0 + 4*tx + dj;
        if (c < NL) C[r*NL + c] = v[di][dj];
      }
    }
  }
  if (uvdst) {
    float wr[4];
    #pragma unroll
    for (int dj = 0; dj < 4; dj++) {
      int c = c0 + 4*tx + dj;
      wr[dj] = (c < NL) ? uvw[c] : 0.f;
    }
    #pragma unroll
    for (int di = 0; di < 4; di++) {
      float s = wr[0]*v[di][0] + wr[1]*v[di][1] + wr[2]*v[di][2] + wr[3]*v[di][3];
      #pragma unroll
      for (int sh = 8; sh; sh >>= 1) s += __shfl_down_sync(0xffffffffu, s, sh, 16);
      int r = r0 + 4*ty + di;
      if (tx == 0 && r < rows) atomicAdd(&uvdst[r], s);
    }
  }
}

// ---------------- K235: pairwise |.| (transposed zout [j][i]) + id ----------
__global__ __launch_bounds__(256)
void k235_mega(const float* __restrict__ disc_w2,
               const float* __restrict__ gat_att,
               const float* __restrict__ gat_bias) {
  __shared__ __align__(16) float sm[2*16*68 + 32];
  int bid = blockIdx.x;
  int tid = threadIdx.x;
  if (bid < 360) {
    int which = bid / 180; int rem = bid % 180;
    int b = rem / 90; rem %= 90;
    int chunk = rem / 9; int t9 = rem % 9;
    int j0 = (t9 / 3) * 64, i0 = (t9 % 3) * 64;   // row = j, col = i
    float (*Pt)[68] = (float(*)[68])sm;
    float (*Qt)[68] = (float(*)[68])(sm + 16*68);
    float* ws = sm + 2*16*68;
    const float *pr, *pc, *wsg; int nrows; float* zout;
    if (which == 0) { pr = g_pjp + b*NN*NL; pc = g_pi + b*NN*NL; wsg = disc_w2; nrows = NN;
                      zout = g_zp + (chunk*2 + b)*192*192; }
    else            { pr = g_xr_cg + b*NM*NL; pc = g_xl_cg + b*NM*NL; wsg = gat_att; nrows = NM;
                      zout = g_zg + (chunk*2 + b)*192*192; }
    int ty = tid >> 4, tx = tid & 15;
    int rr = tid >> 2, g = tid & 3;
    float acc[4][4] = {};
    for (int step = 0; step < 5; step++) {
      int lbase = chunk*80 + step*16;
      float4 pv = make_float4(0.f,0.f,0.f,0.f), qv = pv;
      if (j0 + rr < nrows) pv = *(const float4*)&pr[(j0 + rr)*NL + lbase + g*4];
      if (i0 + rr < nrows) qv = *(const float4*)&pc[(i0 + rr)*NL + lbase + g*4];
      float wreg = (tid < 16) ? wsg[lbase + tid] : 0.f;
      __syncthreads();
      int kb = g*4;
      Pt[kb+0][rr] = pv.x; Pt[kb+1][rr] = pv.y; Pt[kb+2][rr] = pv.z; Pt[kb+3][rr] = pv.w;
      Qt[kb+0][rr] = qv.x; Qt[kb+1][rr] = qv.y; Qt[kb+2][rr] = qv.z; Qt[kb+3][rr] = qv.w;
      if (tid < 16) ws[tid] = wreg;
      __syncthreads();
      #pragma unroll
      for (int k = 0; k < 16; k++) {
        float a = ws[k];
        float4 p = *(const float4*)&Pt[k][4*ty];
        float4 q = *(const float4*)&Qt[k][4*tx];
        float pvv[4] = {p.x, p.y, p.z, p.w};
        float qvv[4] = {q.x, q.y, q.z, q.w};
        #pragma unroll
        for (int di = 0; di < 4; di++)
          #pragma unroll
          for (int dj = 0; dj < 4; dj++)
            acc[di][dj] = fmaf(a, fabsf(pvv[di] + qvv[dj]), acc[di][dj]);
      }
    }
    #pragma unroll
    for (int di = 0; di < 4; di++) {
      int j = j0 + 4*ty + di;
      float4 o = make_float4(acc[di][0], acc[di][1], acc[di][2], acc[di][3]);
      *(float4*)&zout[j*192 + i0 + 4*tx] = o;
    }
  } else {
    // ---- identity-graph transitioner ----
    int q = bid - 360;
    int b = q / NM, j = q % NM;
    float* es   = sm;
    float* red  = sm + 160;
    float* abuf = sm + 416;
    const float* xl = g_xl_id + b*NM*NL;
    const float* xr = g_xr_id + b*NM*NL;
    float* outp = g_agg_id + b*NM*NL;
    if (j < NN) {
      float s1 = 0.f, s2 = 0.f;
      for (int l = tid; l < NL; l += 256) {
        float xrv = xr[j*NL + l];
        float a = gat_att[l];
        float t1 = xl[j*NL + l] + xrv;
        s1 += a * fmaxf(t1, 0.2f * t1);
        float t2 = xl[NN*NL + l] + xrv;
        s2 += a * fmaxf(t2, 0.2f * t2);
      }
      red[tid] = s1; __syncthreads();
      for (int s = 128; s; s >>= 1) { if (tid < s) red[tid] += red[tid + s]; __syncthreads(); }
      float e1 = red[0]; __syncthreads();
      red[tid] = s2; __syncthreads();
      for (int s = 128; s; s >>= 1) { if (tid < s) red[tid] += red[tid + s]; __syncthreads(); }
      float e2 = red[0];
      float m = fmaxf(e1, e2);
      float x1 = expf(e1 - m), x2 = expf(e2 - m);
      float inv = 1.0f / (x1 + x2);
      float al1 = x1 * inv, al2 = x2 * inv;
      for (int l = tid; l < NL; l += 256) {
        float v = al1 * xl[j*NL + l] + al2 * xl[NN*NL + l] + gat_bias[l];
        outp[j*NL + l] = fmaxf(v, 0.f);
      }
    } else {
      int wid = tid >> 5, lane = tid & 31;
      for (int i = wid; i < NM; i += 8) {
        float s = 0.f;
        for (int l = lane; l < NL; l += 32) {
          float t = xl[i*NL + l] + xr[NN*NL + l];
          s += gat_att[l] * fmaxf(t, 0.2f * t);
        }
        for (int sh = 16; sh; sh >>= 1) s += __shfl_xor_sync(0xffffffffu, s, sh);
        if (lane == 0) es[i] = s;
      }
      __syncthreads();
      if (tid == 0) {
        float m = -3.4e38f;
        for (int i = 0; i < NM; i++) m = fmaxf(m, es[i]);
        float sum = 0.f;
        for (int i = 0; i < NM; i++) sum += expf(es[i] - m);
        abuf[0] = m; abuf[1] = 1.0f / sum;
      }
      __syncthreads();
      float m = abuf[0], inv = abuf[1];
      for (int i = tid; i < NM; i += 256) es[i] = expf(es[i] - m) * inv;
      __syncthreads();
      for (int l = tid; l < NL; l += 256) {
        float acc = gat_bias[l];
        for (int i = 0; i < NM; i++) acc += es[i] * xl[i*NL + l];
        outp[NN*NL + l] = fmaxf(acc, 0.f);
      }
    }
  }
}

// ---------------- K3: decide + loss1 + mask + softmax, ONE coalesced pass ---
__global__ void k3_softmax(const float* __restrict__ disc_b2) {
  int warp = (blockIdx.x * blockDim.x + threadIdx.x) >> 5;
  int lane = threadIdx.x & 31;
  if (warp >= NB*NM) return;
  int b = warp / NM, j = warp % NM;
  float b2 = disc_b2[0];
  float vgj = g_vg[b*NM + j];
  float vdj = (j < NN) ? g_vd[b*NN + j] : 0.f;
  float lp = 0.f;
  float ev[5];
  #pragma unroll
  for (int t = 0; t < 5; t++) {
    int i = lane + 32*t;
    float v = -3.4e38f;
    if (i < NM) {
      bool mask;
      if (i < NN && j < NN) {
        float S = 0.f;
        #pragma unroll
        for (int cc = 0; cc < 10; cc++) S += g_zp[((cc*2 + b)*192 + j)*192 + i];
        float z = 0.495f*S + 0.505f*(g_ud[b*NN + i] + vdj) + b2;
        float cgv = (z > g_gumT[(b*NN + j)*NN + i]) ? 1.0f : 0.0f;
        float d = (i == j) ? (1.0f - cgv) : cgv;
        lp += d * d;
        mask = (i == j) || (cgv != 0.0f);
      } else {
        mask = true;          // i == NN or j == NN rows/cols are unmasked
      }
      if (mask) {
        float S2 = 0.f;
        #pragma unroll
        for (int cc = 0; cc < 10; cc++) S2 += g_zg[((cc*2 + b)*192 + j)*192 + i];
        v = 0.6f*(g_ug[b*NM + i] + vgj) + 0.4f*S2;
      } else v = -1e30f;
    }
    ev[t] = v;
  }
  // loss1 reduce (only j<NN warps contribute)
  if (j < NN) {
    float s = lp;
    #pragma unroll
    for (int sh = 16; sh; sh >>= 1) s += __shfl_xor_sync(0xffffffffu, s, sh);
    if (lane == 0) atomicAdd(&g_loss1, s);
  }
  float m = -3.4e38f;
  #pragma unroll
  for (int t = 0; t < 5; t++) m = fmaxf(m, ev[t]);
  #pragma unroll
  for (int s = 16; s; s >>= 1) m = fmaxf(m, __shfl_xor_sync(0xffffffffu, m, s));
  float sum = 0.f;
  #pragma unroll
  for (int t = 0; t < 5; t++) { ev[t] = (ev[t] > -3.0e38f) ? expf(ev[t] - m) : 0.f; sum += ev[t]; }
  #pragma unroll
  for (int s = 16; s; s >>= 1) sum += __shfl_xor_sync(0xffffffffu, sum, s);
  float inv = 1.0f / sum;
  float* aT = g_alphaT + (b*NM + j)*NMP;
  #pragma unroll
  for (int t = 0; t < 5; t++) {
    int i = lane + 32*t;
    if (i < NM) aT[i] = ev[t] * inv;
    else if (i < NMP) aT[i] = 0.f;
  }
}

// ---------------- shared projection body (290x800)@(800x64) 32x32 tile ------
__device__ void proj_body(int q, int mode,
                          const float* __restrict__ A,
                          const float* __restrict__ out_w,
                          const float* __restrict__ out_b,
                          const float* __restrict__ latent,
                          float* __restrict__ d_out,
                          float* sm) {
  int r0 = (q / 2) * 32, c0 = (q % 2) * 32;
  float (*As2)[34] = (float(*)[34])sm;
  float (*Ws)[34]  = (float(*)[34])(sm + 32*34);
  float* red = sm + 2*32*34;
  int tid = threadIdx.x, ty = tid >> 4, tx = tid & 15;
  float a00 = 0.f, a01 = 0.f, a10 = 0.f, a11 = 0.f;
  for (int k0 = 0; k0 < NL; k0 += 32) {
    for (int idx = tid; idx < 1024; idx += 256) {
      int r = idx >> 5, c = idx & 31;
      As2[c][r] = (r0 + r < NB*NM) ? A[(r0 + r)*NL + k0 + c] : 0.f;
      Ws[r][c]  = out_w[(k0 + r)*NC + c0 + c];
    }
    __syncthreads();
    #pragma unroll
    for (int k = 0; k < 32; k++) {
      float2 ar = *(const float2*)&As2[k][2*ty];
      float2 w  = *(const float2*)&Ws[k][2*tx];
      a00 = fmaf(ar.x, w.x, a00); a01 = fmaf(ar.x, w.y, a01);
      a10 = fmaf(ar.y, w.x, a10); a11 = fmaf(ar.y, w.y, a11);
    }
    __syncthreads();
  }
  float y[2][2] = {{a00 + out_b[c0 + 2*tx], a01 + out_b[c0 + 2*tx + 1]},
                   {a10 + out_b[c0 + 2*tx], a11 + out_b[c0 + 2*tx + 1]}};
  float lp = 0.f;
  #pragma unroll
  for (int di = 0; di < 2; di++) {
    int r = r0 + 2*ty + di;
    if (r < NB*NM) {
      int b = r / NM, n = r % NM;
      if (n < NN) {
        #pragma unroll
        for (int dj = 0; dj < 2; dj++) {
          int c = c0 + 2*tx + dj;
          int oidx = (b*NC + c)*NN + n;
          if (mode == 1) d_out[oidx] = y[di][dj];
          else { float d = latent[oidx] - y[di][dj]; lp += d*d; }
        }
      }
    }
  }
  if (mode == 0) {
    red[tid] = lp; __syncthreads();
    for (int s = 128; s; s >>= 1) { if (tid < s) red[tid] += red[tid + s]; __syncthreads(); }
    if (tid == 0) atomicAdd(&g_loss2, red[0]);
  }
}

// ---------------- K4: agg_cg GEMM (78) + y_id projection/loss2 (20) ---------
__global__ __launch_bounds__(256)
void k4_agg(const float* __restrict__ gat_bias,
            const float* __restrict__ out_w,
            const float* __restrict__ out_b,
            const float* __restrict__ latent) {
  __shared__ __align__(16) float sm[2*32*34 + 256];
  int bid = blockIdx.x;
  if (bid >= 78) {
    proj_body(bid - 78, 0, g_agg_id, out_w, out_b, latent, nullptr, sm);
    return;
  }
  float (*ATs)[68] = (float(*)[68])sm;
  float (*Xs)[68]  = (float(*)[68])(sm + 16*68);
  int b = bid / 39, rem = bid % 39;
  int j0 = (rem / 13) * 64, l0 = (rem % 13) * 64;
  int tid = threadIdx.x;
  int ty = tid >> 4, tx = tid & 15;
  int rr = tid >> 2, g = tid & 3;
  const float* aT = g_alphaT + b*NM*NMP;
  const float* xl = g_xl_cg + b*NM*NL;
  float acc[4][4] = {};
  for (int step = 0; step < 9; step++) {
    int ib = step*16;
    float4 av = make_float4(0.f,0.f,0.f,0.f);
    if (j0 + rr < NM) av = *(const float4*)&aT[(j0 + rr)*NMP + ib + g*4];
    int fi = tid >> 4, c4 = (tid & 15) * 4;
    float4 xv = make_float4(0.f,0.f,0.f,0.f);
    if (l0 + c4 < NL) xv = *(const float4*)&xl[(ib + fi)*NL + l0 + c4];
    __syncthreads();
    int kb = g*4;
    ATs[kb+0][rr] = av.x; ATs[kb+1][rr] = av.y; ATs[kb+2][rr] = av.z; ATs[kb+3][rr] = av.w;
    *(float4*)&Xs[fi][c4] = xv;
    __syncthreads();
    #pragma unroll
    for (int k = 0; k < 16; k++) {
      float4 a4 = *(const float4*)&ATs[k][4*ty];
      float4 x4 = *(const float4*)&Xs[k][4*tx];
      float avv[4] = {a4.x, a4.y, a4.z, a4.w};
      float xvv[4] = {x4.x, x4.y, x4.z, x4.w};
      #pragma unroll
      for (int di = 0; di < 4; di++)
        #pragma unroll
        for (int dj = 0; dj < 4; dj++)
          acc[di][dj] = fmaf(avv[di], xvv[dj], acc[di][dj]);
    }
  }
  {
    float a144[4], x144[4];
    #pragma unroll
    for (int di = 0; di < 4; di++) {
      int j = j0 + 4*ty + di;
      a144[di] = (j < NM) ? aT[j*NMP + 144] : 0.f;
    }
    #pragma unroll
    for (int dj = 0; dj < 4; dj++) {
      int l = l0 + 4*tx + dj;
      x144[dj] = (l < NL) ? xl[144*NL + l] : 0.f;
    }
    #pragma unroll
    for (int di = 0; di < 4; di++)
      #pragma unroll
      for (int dj = 0; dj < 4; dj++)
        acc[di][dj] = fmaf(a144[di], x144[dj], acc[di][dj]);
  }
  float* outp = g_agg_cg + b*NM*NL;
  #pragma unroll
  for (int di = 0; di < 4; di++) {
    int j = j0 + 4*ty + di;
    if (j < NM) {
      #pragma unroll
      for (int dj = 0; dj < 4; dj++) {
        int l = l0 + 4*tx + dj;
        if (l < NL) outp[j*NL + l] = fmaxf(acc[di][dj] + gat_bias[l], 0.f);
      }
    }
  }
}

// ---------------- K6: y_cg projection -> d_out + loss scalar ----------------
__global__ void k6_out(const float* __restrict__ out_w,
                       const float* __restrict__ out_b,
                       const float* __restrict__ latent,
                       float* __restrict__ d_out) {
  __shared__ __align__(16) float sm[2*32*34 + 256];
  if (blockIdx.x == 0 && threadIdx.x == 0)
    d_out[NB*NN*NC] = g_loss1 / (float)(NB*NN*NN) + g_loss2 / (float)(NB*NN*NC);
  proj_body(blockIdx.x, 1, g_agg_cg, out_w, out_b, latent, d_out, sm);
}

// ---------------- launch ----------------------------------------------------
extern "C" void kernel_launch(void* const* d_in, const int* in_sizes, int n_in,
                              void* d_out, int out_size) {
  (void)in_sizes; (void)n_in; (void)out_size;
  const float* latent    = (const float*)d_in[0];
  const float* a_dense_b = (const float*)d_in[2];
  const float* disc_w1   = (const float*)d_in[3];
  const float* disc_b1   = (const float*)d_in[4];
  const float* disc_w2   = (const float*)d_in[5];
  const float* disc_b2   = (const float*)d_in[6];
  const float* gat_wl    = (const float*)d_in[7];
  const float* gat_bl    = (const float*)d_in[8];
  const float* gat_wr    = (const float*)d_in[9];
  const float* gat_br    = (const float*)d_in[10];
  const float* gat_att   = (const float*)d_in[11];
  const float* gat_bias  = (const float*)d_in[12];
  const float* out_w     = (const float*)d_in[13];
  const float* out_b     = (const float*)d_in[14];
  float* out = (float*)d_out;

  uint32_t kg0, kg1, n10, n11, n20, n21, a, b;
  tf2x32(0u, 42u, 0u, 0u, a, b); kg0 = a; kg1 = b;
  tf2x32(0u, 42u, 0u, 1u, a, b); n10 = a; n11 = b;
  tf2x32(0u, 42u, 0u, 2u, a, b); n20 = a; n21 = b;

  int k0_threads = NB*NN*NC + NL + 2*NB*NM*NC + 2*NB*NN + 2*NB*NM + NB*NN*NN;
  k0_prep<<<(k0_threads + 255)/256, 256>>>(latent, a_dense_b, disc_w1, disc_b1,
                                           kg0, kg1, n10, n11, n20, n21);
  k1_gemm64<<<dim3(5, 13, 6), 256>>>(disc_w1, gat_wl, gat_wr, gat_bl, gat_br,
                                     disc_w2, gat_att);
  k235_mega<<<360 + NB*NM, 256>>>(disc_w2, gat_att, gat_bias);
  k3_softmax<<<37, 256>>>(disc_b2);
  k4_agg<<<78 + 20, 256>>>(gat_bias, out_w, out_b, latent);
  k6_out<<<20, 256>>>(out_w, out_b, latent, out);
}

// round 13
// speedup vs baseline: 1.0086x; 1.0086x over previous
#include <cuda_runtime.h>
#include <cstdint>
#include <math.h>

#define NB 2
#define NC 64
#define NN 144
#define NM 145
#define NL 800
#define NMP 148   // padded alphaT row stride (float4-aligned)

// ---------------- scratch (device globals; no allocation) -------------------
__device__ float g_pos[NB*NN*NC];
__device__ float g_pa[NL];
__device__ float g_nodes_cg[NB*NM*NC];
__device__ float g_nodes_id[NB*NM*NC];
__device__ float g_pi [NB*NN*NL];
__device__ float g_pjp[NB*NN*NL];
__device__ float g_xl_cg[NB*NM*NL];
__device__ float g_xr_cg[NB*NM*NL];
__device__ float g_xl_id[NB*NM*NL];
__device__ float g_xr_id[NB*NM*NL];
__device__ float g_cgT[NB*NN*NN];         // hard sample, TRANSPOSED [b][j][i]
__device__ float g_gum[NB*NN*NN];         // precomputed gumbel0 - gumbel1
__device__ float g_alphaT[NB*NM*NMP];
__device__ float g_agg_cg[NB*NM*NL];
__device__ float g_agg_id[NB*NM*NL];
__device__ float g_zp[10*2*192*192];      // disc |.| partials, [chunk][b][i][j]
__device__ float g_zg[10*2*192*192];      // gat  |.| partials, [chunk][b][j][i] (TRANSPOSED)
__device__ float g_ud[NB*NN], g_vd[NB*NN];
__device__ float g_ug[NB*NM], g_vg[NB*NM];
__device__ float g_loss1, g_loss2;

// ---------------- threefry2x32 (JAX-exact, partitionable) -------------------
__host__ __device__ __forceinline__ void tf2x32(uint32_t k0, uint32_t k1,
                                                uint32_t x0, uint32_t x1,
                                                uint32_t &o0, uint32_t &o1) {
  uint32_t k2 = k0 ^ k1 ^ 0x1BD11BDAu;
  x0 += k0; x1 += k1;
#define TFR(r) { x0 += x1; x1 = (x1 << (r)) | (x1 >> (32 - (r))); x1 ^= x0; }
  TFR(13) TFR(15) TFR(26) TFR(6)
  x0 += k1; x1 += k2 + 1u;
  TFR(17) TFR(29) TFR(16) TFR(24)
  x0 += k2; x1 += k0 + 2u;
  TFR(13) TFR(15) TFR(26) TFR(6)
  x0 += k0; x1 += k1 + 3u;
  TFR(17) TFR(29) TFR(16) TFR(24)
  x0 += k1; x1 += k2 + 4u;
  TFR(13) TFR(15) TFR(26) TFR(6)
  x0 += k2; x1 += k0 + 5u;
#undef TFR
  o0 = x0; o1 = x1;
}

__device__ __forceinline__ uint32_t jx_bits(uint32_t k0, uint32_t k1, uint32_t f) {
  uint32_t o0, o1; tf2x32(k0, k1, 0u, f, o0, o1); return o0 ^ o1;
}
__device__ __forceinline__ float jx_u01(uint32_t bits) {
  return __uint_as_float((bits >> 9) | 0x3F800000u) - 1.0f;
}
__device__ __forceinline__ float jx_gumbel(uint32_t k0, uint32_t k1, uint32_t f) {
  float u01 = jx_u01(jx_bits(k0, k1, f));
  const float tiny = 1.17549435e-38f;
  float u = fmaxf(tiny, u01 + tiny);
  return -logf(-logf(u));
}
__device__ __forceinline__ float jx_normal(uint32_t k0, uint32_t k1, uint32_t f) {
  float u01 = jx_u01(jx_bits(k0, k1, f));
  const float lo = -0.99999994f;
  float u = fmaxf(lo, u01 * 2.0f + lo);
  return 1.41421356f * erfinvf(u);
}

// ---------------- K0: pos, pa, noisy nodes, gumbel diffs, zero u/v ----------
__global__ void k0_prep(const float* __restrict__ latent,
                        const float* __restrict__ a_dense_b,
                        const float* __restrict__ disc_w1,
                        const float* __restrict__ disc_b1,
                        uint32_t kg0, uint32_t kg1,
                        uint32_t n10, uint32_t n11, uint32_t n20, uint32_t n21) {
  int tid = blockIdx.x * blockDim.x + threadIdx.x;
  if (tid == 0) { g_loss1 = 0.f; g_loss2 = 0.f; }
  const float t = -logf(10000.0f) / 64.0f;
  const int R0 = NB*NN*NC;
  const int R1 = R0 + NL;
  const int R2 = R1 + 2*NB*NM*NC;
  const int R3 = R2 + 2*NB*NN + 2*NB*NM;
  const int R4 = R3 + NB*NN*NN;
  if (tid < R0) {
    int b = tid / (NN*NC), r = tid % (NN*NC);
    int n = r >> 6, c = r & 63;
    int h = n / 12, w = n % 12;
    float lat = latent[((b*NC + c)*12 + h)*12 + w];
    float dv = expf((float)(2*(c >> 1)) * t);
    float ang = (float)n * dv;
    float pe = (c & 1) ? cosf(ang) : sinf(ang);
    g_pos[tid] = lat + pe;
  } else if (tid < R1) {
    int l = tid - R0;
    float s = disc_b1[l];
    #pragma unroll 8
    for (int c = 0; c < NC; c++) s += a_dense_b[c] * disc_w1[(2*NC + c)*NL + l];
    g_pa[l] = s;
  } else if (tid < R2) {
    int q = tid - R1;
    int which = q / (NB*NM*NC);
    int f = q % (NB*NM*NC);
    int b = f / (NM*NC), r = f % (NM*NC);
    int m = r >> 6, c = r & 63;
    float base;
    if (m < NN) {
      int h = m / 12, w = m % 12;
      float lat = latent[((b*NC + c)*12 + h)*12 + w];
      float dv = expf((float)(2*(c >> 1)) * t);
      float ang = (float)m * dv;
      float pe = (c & 1) ? cosf(ang) : sinf(ang);
      base = lat + pe;
    } else {
      base = a_dense_b[c];
    }
    uint32_t k0 = which ? n20 : n10, k1 = which ? n21 : n11;
    float noise = jx_normal(k0, k1, (uint32_t)f);
    (which ? g_nodes_id : g_nodes_cg)[f] = base + noise;
  } else if (tid < R3) {
    int q = tid - R2;
    if (q < NB*NN) g_ud[q] = 0.f;
    else if (q < 2*NB*NN) g_vd[q - NB*NN] = 0.f;
    else if (q < 2*NB*NN + NB*NM) g_ug[q - 2*NB*NN] = 0.f;
    else g_vg[q - 2*NB*NN - NB*NM] = 0.f;
  } else if (tid < R4) {
    int gidx = tid - R3;
    uint32_t f = (uint32_t)(gidx * 2);
    float gg0 = jx_gumbel(kg0, kg1, f);
    float gg1 = jx_gumbel(kg0, kg1, f + 1u);
    g_gum[gidx] = gg0 - gg1;
  }
}

// ---------------- K1: six (rows x 64)@(64 x 800) GEMMs, 64x64 tile, 4x4 -----
__global__ __launch_bounds__(256)
void k1_gemm64(const float* __restrict__ disc_w1,
               const float* __restrict__ gat_wl,
               const float* __restrict__ gat_wr,
               const float* __restrict__ gat_bl,
               const float* __restrict__ gat_br,
               const float* __restrict__ disc_w2,
               const float* __restrict__ gat_att) {
  __shared__ __align__(16) float Ast[64][68];   // [k][row]
  __shared__ __align__(16) float Ws[64][68];    // [k][col]
  const float *A, *W, *bias; float *C; int rows;
  const float *uvw = nullptr; float *uvdst = nullptr;
  switch (blockIdx.z) {
    case 0:  A = g_pos;      W = disc_w1;          bias = nullptr; C = g_pi;    rows = NB*NN;
             uvw = disc_w2; uvdst = g_ud; break;
    case 1:  A = g_pos;      W = disc_w1 + NC*NL;  bias = g_pa;    C = g_pjp;   rows = NB*NN;
             uvw = disc_w2; uvdst = g_vd; break;
    case 2:  A = g_nodes_cg; W = gat_wl;           bias = gat_bl;  C = g_xl_cg; rows = NB*NM;
             uvw = gat_att; uvdst = g_ug; break;
    case 3:  A = g_nodes_cg; W = gat_wr;           bias = gat_br;  C = g_xr_cg; rows = NB*NM;
             uvw = gat_att; uvdst = g_vg; break;
    case 4:  A = g_nodes_id; W = gat_wl;           bias = gat_bl;  C = g_xl_id; rows = NB*NM; break;
    default: A = g_nodes_id; W = gat_wr;           bias = gat_br;  C = g_xr_id; rows = NB*NM; break;
  }
  int r0 = blockIdx.x * 64, c0 = blockIdx.y * 64;
  if (r0 >= rows) return;
  int tid = threadIdx.x;
  int ty = tid >> 4, tx = tid & 15;
  int rr = tid >> 2, g = tid & 3;
  #pragma unroll
  for (int m = 0; m < 4; m++) {
    int k = g*16 + m*4;
    float4 av = make_float4(0.f, 0.f, 0.f, 0.f);
    if (r0 + rr < rows) av = *(const float4*)&A[(r0 + rr)*NC + k];
    Ast[k+0][rr] = av.x; Ast[k+1][rr] = av.y; Ast[k+2][rr] = av.z; Ast[k+3][rr] = av.w;
  }
  #pragma unroll
  for (int u = 0; u < 4; u++) {
    int idx = tid + u*256;
    int k = idx >> 4, c4 = (idx & 15) * 4;
    float4 wv = make_float4(0.f, 0.f, 0.f, 0.f);
    if (c0 + c4 < NL) wv = *(const float4*)&W[k*NL + c0 + c4];
    *(float4*)&Ws[k][c4] = wv;
  }
  __syncthreads();
  float acc[4][4] = {};
  #pragma unroll
  for (int k = 0; k < 64; k++) {
    float4 x = *(const float4*)&Ast[k][4*ty];
    float4 w = *(const float4*)&Ws[k][4*tx];
    float xv[4] = {x.x, x.y, x.z, x.w};
    float wv[4] = {w.x, w.y, w.z, w.w};
    #pragma unroll
    for (int di = 0; di < 4; di++)
      #pragma unroll
      for (int dj = 0; dj < 4; dj++)
        acc[di][dj] = fmaf(xv[di], wv[dj], acc[di][dj]);
  }
  float bb[4], v[4][4];
  #pragma unroll
  for (int dj = 0; dj < 4; dj++) {
    int c = c0 + 4*tx + dj;
    bb[dj] = (bias && c < NL) ? bias[c] : 0.f;
  }
  #pragma unroll
  for (int di = 0; di < 4; di++) {
    int r = r0 + 4*ty + di;
    #pragma unroll
    for (int dj = 0; dj < 4; dj++) v[di][dj] = acc[di][dj] + bb[dj];
    if (r < rows) {
      #pragma unroll
      for (int dj = 0; dj < 4; dj++) {
        int c = c0 + 4*tx + dj;
        if (c < NL) C[r*NL + c] = v[di][dj];
      }
    }
  }
  if (uvdst) {
    float wr[4];
    #pragma unroll
    for (int dj = 0; dj < 4; dj++) {
      int c = c0 + 4*tx + dj;
      wr[dj] = (c < NL) ? uvw[c] : 0.f;
    }
    #pragma unroll
    for (int di = 0; di < 4; di++) {
      float s = wr[0]*v[di][0] + wr[1]*v[di][1] + wr[2]*v[di][2] + wr[3]*v[di][3];
      #pragma unroll
      for (int sh = 8; sh; sh >>= 1) s += __shfl_down_sync(0xffffffffu, s, sh, 16);
      int r = r0 + 4*ty + di;
      if (tx == 0 && r < rows) atomicAdd(&uvdst[r], s);
    }
  }
}

// ---------------- K235: pairwise |.| (disc [i][j], gat TRANSPOSED [j][i]) ---
__global__ __launch_bounds__(256)
void k235_mega(const float* __restrict__ disc_w2,
               const float* __restrict__ gat_att,
               const float* __restrict__ gat_bias) {
  __shared__ __align__(16) float sm[2*16*68 + 32];
  int bid = blockIdx.x;
  int tid = threadIdx.x;
  if (bid < 360) {
    int which = bid / 180; int rem = bid % 180;
    int b = rem / 90; rem %= 90;
    int chunk = rem / 9; int t9 = rem % 9;
    int r0t = (t9 / 3) * 64, c0t = (t9 % 3) * 64;
    float (*Pt)[68] = (float(*)[68])sm;
    float (*Qt)[68] = (float(*)[68])(sm + 16*68);
    float* ws = sm + 2*16*68;
    const float *pr, *pc, *wsg; int nrows; float* zout;
    if (which == 0) {
      // disc: rows = i (from pi), cols = j (from pjp) -> zp[i][j]
      pr = g_pi  + b*NN*NL; pc = g_pjp + b*NN*NL; wsg = disc_w2; nrows = NN;
      zout = g_zp + (chunk*2 + b)*192*192;
    } else {
      // gat: rows = j (from xr), cols = i (from xl) -> zg[j][i]  (TRANSPOSED)
      pr = g_xr_cg + b*NM*NL; pc = g_xl_cg + b*NM*NL; wsg = gat_att; nrows = NM;
      zout = g_zg + (chunk*2 + b)*192*192;
    }
    int ty = tid >> 4, tx = tid & 15;
    int rr = tid >> 2, g = tid & 3;
    float acc[4][4] = {};
    for (int step = 0; step < 5; step++) {
      int lbase = chunk*80 + step*16;
      float4 pv = make_float4(0.f,0.f,0.f,0.f), qv = pv;
      if (r0t + rr < nrows) pv = *(const float4*)&pr[(r0t + rr)*NL + lbase + g*4];
      if (c0t + rr < nrows) qv = *(const float4*)&pc[(c0t + rr)*NL + lbase + g*4];
      float wreg = (tid < 16) ? wsg[lbase + tid] : 0.f;
      __syncthreads();
      int kb = g*4;
      Pt[kb+0][rr] = pv.x; Pt[kb+1][rr] = pv.y; Pt[kb+2][rr] = pv.z; Pt[kb+3][rr] = pv.w;
      Qt[kb+0][rr] = qv.x; Qt[kb+1][rr] = qv.y; Qt[kb+2][rr] = qv.z; Qt[kb+3][rr] = qv.w;
      if (tid < 16) ws[tid] = wreg;
      __syncthreads();
      #pragma unroll
      for (int k = 0; k < 16; k++) {
        float a = ws[k];
        float4 p = *(const float4*)&Pt[k][4*ty];
        float4 q = *(const float4*)&Qt[k][4*tx];
        float pvv[4] = {p.x, p.y, p.z, p.w};
        float qvv[4] = {q.x, q.y, q.z, q.w};
        #pragma unroll
        for (int di = 0; di < 4; di++)
          #pragma unroll
          for (int dj = 0; dj < 4; dj++)
            acc[di][dj] = fmaf(a, fabsf(pvv[di] + qvv[dj]), acc[di][dj]);
      }
    }
    #pragma unroll
    for (int di = 0; di < 4; di++) {
      int r = r0t + 4*ty + di;
      float4 o = make_float4(acc[di][0], acc[di][1], acc[di][2], acc[di][3]);
      *(float4*)&zout[r*192 + c0t + 4*tx] = o;
    }
  } else {
    // ---- identity-graph transitioner ----
    int q = bid - 360;
    int b = q / NM, j = q % NM;
    float* es   = sm;
    float* red  = sm + 160;
    float* abuf = sm + 416;
    const float* xl = g_xl_id + b*NM*NL;
    const float* xr = g_xr_id + b*NM*NL;
    float* outp = g_agg_id + b*NM*NL;
    if (j < NN) {
      float s1 = 0.f, s2 = 0.f;
      for (int l = tid; l < NL; l += 256) {
        float xrv = xr[j*NL + l];
        float a = gat_att[l];
        float t1 = xl[j*NL + l] + xrv;
        s1 += a * fmaxf(t1, 0.2f * t1);
        float t2 = xl[NN*NL + l] + xrv;
        s2 += a * fmaxf(t2, 0.2f * t2);
      }
      red[tid] = s1; __syncthreads();
      for (int s = 128; s; s >>= 1) { if (tid < s) red[tid] += red[tid + s]; __syncthreads(); }
      float e1 = red[0]; __syncthreads();
      red[tid] = s2; __syncthreads();
      for (int s = 128; s; s >>= 1) { if (tid < s) red[tid] += red[tid + s]; __syncthreads(); }
      float e2 = red[0];
      float m = fmaxf(e1, e2);
      float x1 = expf(e1 - m), x2 = expf(e2 - m);
      float inv = 1.0f / (x1 + x2);
      float al1 = x1 * inv, al2 = x2 * inv;
      for (int l = tid; l < NL; l += 256) {
        float v = al1 * xl[j*NL + l] + al2 * xl[NN*NL + l] + gat_bias[l];
        outp[j*NL + l] = fmaxf(v, 0.f);
      }
    } else {
      int wid = tid >> 5, lane = tid & 31;
      for (int i = wid; i < NM; i += 8) {
        float s = 0.f;
        for (int l = lane; l < NL; l += 32) {
          float t = xl[i*NL + l] + xr[NN*NL + l];
          s += gat_att[l] * fmaxf(t, 0.2f * t);
        }
        for (int sh = 16; sh; sh >>= 1) s += __shfl_xor_sync(0xffffffffu, s, sh);
        if (lane == 0) es[i] = s;
      }
      __syncthreads();
      if (tid == 0) {
        float m = -3.4e38f;
        for (int i = 0; i < NM; i++) m = fmaxf(m, es[i]);
        float sum = 0.f;
        for (int i = 0; i < NM; i++) sum += expf(es[i] - m);
        abuf[0] = m; abuf[1] = 1.0f / sum;
      }
      __syncthreads();
      float m = abuf[0], inv = abuf[1];
      for (int i = tid; i < NM; i += 256) es[i] = expf(es[i] - m) * inv;
      __syncthreads();
      for (int l = tid; l < NL; l += 256) {
        float acc = gat_bias[l];
        for (int i = 0; i < NM; i++) acc += es[i] * xl[i*NL + l];
        outp[NN*NL + l] = fmaxf(acc, 0.f);
      }
    }
  }
}

// ---------------- K2b: combine -> compare vs gumbel diff + loss1 ------------
__global__ void k2b_decide(const float* __restrict__ disc_b2) {
  __shared__ float red[256];
  int tid = threadIdx.x;
  int gidx = blockIdx.x * 256 + tid;
  float lp = 0.f;
  if (gidx < NB*NN*NN) {
    int b = gidx / (NN*NN), r = gidx % (NN*NN);
    int i = r / NN, j = r % NN;
    float S = 0.f;
    #pragma unroll
    for (int cc = 0; cc < 10; cc++) S += g_zp[((cc*2 + b)*192 + i)*192 + j];
    float z = 0.495f*S + 0.505f*(g_ud[b*NN + i] + g_vd[b*NN + j]) + disc_b2[0];
    float cgv = (z > g_gum[gidx]) ? 1.0f : 0.0f;
    g_cgT[(b*NN + j)*NN + i] = cgv;     // transposed store (scattered, ok)
    float d = (i == j) ? (1.0f - cgv) : cgv;
    lp = d * d;
  }
  red[tid] = lp; __syncthreads();
  for (int s = 128; s; s >>= 1) { if (tid < s) red[tid] += red[tid + s]; __syncthreads(); }
  if (tid == 0) atomicAdd(&g_loss1, red[0]);
}

// ---------------- K35: mask + column softmax (coalesced zg[j][i]) -----------
__global__ void k35_softmax() {
  int warp = (blockIdx.x * blockDim.x + threadIdx.x) >> 5;
  int lane = threadIdx.x & 31;
  if (warp >= NB*NM) return;
  int b = warp / NM, j = warp % NM;
  float vgj = g_vg[b*NM + j];
  float ev[5];
  #pragma unroll
  for (int t = 0; t < 5; t++) {
    int i = lane + 32*t;
    float v = -3.4e38f;
    if (i < NM) {
      bool mask = (i == NN) || (j == NN) || (i == j);
      if (!mask) mask = g_cgT[(b*NN + j)*NN + i] != 0.0f;   // coalesced
      if (mask) {
        float S = 0.f;
        #pragma unroll
        for (int cc = 0; cc < 10; cc++) S += g_zg[((cc*2 + b)*192 + j)*192 + i];  // coalesced
        v = 0.6f*(g_ug[b*NM + i] + vgj) + 0.4f*S;
      } else v = -1e30f;
    }
    ev[t] = v;
  }
  float m = -3.4e38f;
  #pragma unroll
  for (int t = 0; t < 5; t++) m = fmaxf(m, ev[t]);
  #pragma unroll
  for (int s = 16; s; s >>= 1) m = fmaxf(m, __shfl_xor_sync(0xffffffffu, m, s));
  float sum = 0.f;
  #pragma unroll
  for (int t = 0; t < 5; t++) { ev[t] = (ev[t] > -3.0e38f) ? expf(ev[t] - m) : 0.f; sum += ev[t]; }
  #pragma unroll
  for (int s = 16; s; s >>= 1) sum += __shfl_xor_sync(0xffffffffu, sum, s);
  float inv = 1.0f / sum;
  float* aT = g_alphaT + (b*NM + j)*NMP;
  #pragma unroll
  for (int t = 0; t < 5; t++) {
    int i = lane + 32*t;
    if (i < NM) aT[i] = ev[t] * inv;
    else if (i < NMP) aT[i] = 0.f;
  }
}

// ---------------- shared projection body (290x800)@(800x64) 32x32 tile ------
// mode 0: id -> loss2 partial vs latent ; mode 1: cg -> write d_out
__device__ void proj_body(int q, int mode,
                          const float* __restrict__ A,
                          const float* __restrict__ out_w,
                          const float* __restrict__ out_b,
                          const float* __restrict__ latent,
                          float* __restrict__ d_out,
                          float* sm) {
  int r0 = (q / 2) * 32, c0 = (q % 2) * 32;
  float (*As2)[34] = (float(*)[34])sm;
  float (*Ws)[34]  = (float(*)[34])(sm + 32*34);
  float* red = sm + 2*32*34;
  int tid = threadIdx.x, ty = tid >> 4, tx = tid & 15;
  float a00 = 0.f, a01 = 0.f, a10 = 0.f, a11 = 0.f;
  for (int k0 = 0; k0 < NL; k0 += 32) {
    for (int idx = tid; idx < 1024; idx += 256) {
      int r = idx >> 5, c = idx & 31;
      As2[c][r] = (r0 + r < NB*NM) ? A[(r0 + r)*NL + k0 + c] : 0.f;
      Ws[r][c]  = out_w[(k0 + r)*NC + c0 + c];
    }
    __syncthreads();
    #pragma unroll
    for (int k = 0; k < 32; k++) {
      float2 ar = *(const float2*)&As2[k][2*ty];
      float2 w  = *(const float2*)&Ws[k][2*tx];
      a00 = fmaf(ar.x, w.x, a00); a01 = fmaf(ar.x, w.y, a01);
      a10 = fmaf(ar.y, w.x, a10); a11 = fmaf(ar.y, w.y, a11);
    }
    __syncthreads();
  }
  float y[2][2] = {{a00 + out_b[c0 + 2*tx], a01 + out_b[c0 + 2*tx + 1]},
                   {a10 + out_b[c0 + 2*tx], a11 + out_b[c0 + 2*tx + 1]}};
  float lp = 0.f;
  #pragma unroll
  for (int di = 0; di < 2; di++) {
    int r = r0 + 2*ty + di;
    if (r < NB*NM) {
      int b = r / NM, n = r % NM;
      if (n < NN) {
        #pragma unroll
        for (int dj = 0; dj < 2; dj++) {
          int c = c0 + 2*tx + dj;
          int oidx = (b*NC + c)*NN + n;
          if (mode == 1) d_out[oidx] = y[di][dj];
          else { float d = latent[oidx] - y[di][dj]; lp += d*d; }
        }
      }
    }
  }
  if (mode == 0) {
    red[tid] = lp; __syncthreads();
    for (int s = 128; s; s >>= 1) { if (tid < s) red[tid] += red[tid + s]; __syncthreads(); }
    if (tid == 0) atomicAdd(&g_loss2, red[0]);
  }
}

// ---------------- K4: agg_cg GEMM (78) + y_id projection/loss2 (20) ---------
__global__ __launch_bounds__(256)
void k4_agg(const float* __restrict__ gat_bias,
            const float* __restrict__ out_w,
            const float* __restrict__ out_b,
            const float* __restrict__ latent) {
  __shared__ __align__(16) float sm[2*32*34 + 256];
  int bid = blockIdx.x;
  if (bid >= 78) {
    proj_body(bid - 78, 0, g_agg_id, out_w, out_b, latent, nullptr, sm);
    return;
  }
  float (*ATs)[68] = (float(*)[68])sm;
  float (*Xs)[68]  = (float(*)[68])(sm + 16*68);
  int b = bid / 39, rem = bid % 39;
  int j0 = (rem / 13) * 64, l0 = (rem % 13) * 64;
  int tid = threadIdx.x;
  int ty = tid >> 4, tx = tid & 15;
  int rr = tid >> 2, g = tid & 3;
  const float* aT = g_alphaT + b*NM*NMP;
  const float* xl = g_xl_cg + b*NM*NL;
  float acc[4][4] = {};
  for (int step = 0; step < 9; step++) {
    int ib = step*16;
    float4 av = make_float4(0.f,0.f,0.f,0.f);
    if (j0 + rr < NM) av = *(const float4*)&aT[(j0 + rr)*NMP + ib + g*4];
    int fi = tid >> 4, c4 = (tid & 15) * 4;
    float4 xv = make_float4(0.f,0.f,0.f,0.f);
    if (l0 + c4 < NL) xv = *(const float4*)&xl[(ib + fi)*NL + l0 + c4];
    __syncthreads();
    int kb = g*4;
    ATs[kb+0][rr] = av.x; ATs[kb+1][rr] = av.y; ATs[kb+2][rr] = av.z; ATs[kb+3][rr] = av.w;
    *(float4*)&Xs[fi][c4] = xv;
    __syncthreads();
    #pragma unroll
    for (int k = 0; k < 16; k++) {
      float4 a4 = *(const float4*)&ATs[k][4*ty];
      float4 x4 = *(const float4*)&Xs[k][4*tx];
      float avv[4] = {a4.x, a4.y, a4.z, a4.w};
      float xvv[4] = {x4.x, x4.y, x4.z, x4.w};
      #pragma unroll
      for (int di = 0; di < 4; di++)
        #pragma unroll
        for (int dj = 0; dj < 4; dj++)
          acc[di][dj] = fmaf(avv[di], xvv[dj], acc[di][dj]);
    }
  }
  {
    float a144[4], x144[4];
    #pragma unroll
    for (int di = 0; di < 4; di++) {
      int j = j0 + 4*ty + di;
      a144[di] = (j < NM) ? aT[j*NMP + 144] : 0.f;
    }
    #pragma unroll
    for (int dj = 0; dj < 4; dj++) {
      int l = l0 + 4*tx + dj;
      x144[dj] = (l < NL) ? xl[144*NL + l] : 0.f;
    }
    #pragma unroll
    for (int di = 0; di < 4; di++)
      #pragma unroll
      for (int dj = 0; dj < 4; dj++)
        acc[di][dj] = fmaf(a144[di], x144[dj], acc[di][dj]);
  }
  float* outp = g_agg_cg + b*NM*NL;
  #pragma unroll
  for (int di = 0; di < 4; di++) {
    int j = j0 + 4*ty + di;
    if (j < NM) {
      #pragma unroll
      for (int dj = 0; dj < 4; dj++) {
        int l = l0 + 4*tx + dj;
        if (l < NL) outp[j*NL + l] = fmaxf(acc[di][dj] + gat_bias[l], 0.f);
      }
    }
  }
}

// ---------------- K6: y_cg projection -> d_out + loss scalar ----------------
__global__ void k6_out(const float* __restrict__ out_w,
                       const float* __restrict__ out_b,
                       const float* __restrict__ latent,
                       float* __restrict__ d_out) {
  __shared__ __align__(16) float sm[2*32*34 + 256];
  if (blockIdx.x == 0 && threadIdx.x == 0)
    d_out[NB*NN*NC] = g_loss1 / (float)(NB*NN*NN) + g_loss2 / (float)(NB*NN*NC);
  proj_body(blockIdx.x, 1, g_agg_cg, out_w, out_b, latent, d_out, sm);
}

// ---------------- launch ----------------------------------------------------
extern "C" void kernel_launch(void* const* d_in, const int* in_sizes, int n_in,
                              void* d_out, int out_size) {
  (void)in_sizes; (void)n_in; (void)out_size;
  const float* latent    = (const float*)d_in[0];
  const float* a_dense_b = (const float*)d_in[2];
  const float* disc_w1   = (const float*)d_in[3];
  const float* disc_b1   = (const float*)d_in[4];
  const float* disc_w2   = (const float*)d_in[5];
  const float* disc_b2   = (const float*)d_in[6];
  const float* gat_wl    = (const float*)d_in[7];
  const float* gat_bl    = (const float*)d_in[8];
  const float* gat_wr    = (const float*)d_in[9];
  const float* gat_br    = (const float*)d_in[10];
  const float* gat_att   = (const float*)d_in[11];
  const float* gat_bias  = (const float*)d_in[12];
  const float* out_w     = (const float*)d_in[13];
  const float* out_b     = (const float*)d_in[14];
  float* out = (float*)d_out;

  uint32_t kg0, kg1, n10, n11, n20, n21, a, b;
  tf2x32(0u, 42u, 0u, 0u, a, b); kg0 = a; kg1 = b;
  tf2x32(0u, 42u, 0u, 1u, a, b); n10 = a; n11 = b;
  tf2x32(0u, 42u, 0u, 2u, a, b); n20 = a; n21 = b;

  int k0_threads = NB*NN*NC + NL + 2*NB*NM*NC + 2*NB*NN + 2*NB*NM + NB*NN*NN;
  k0_prep<<<(k0_threads + 255)/256, 256>>>(latent, a_dense_b, disc_w1, disc_b1,
                                           kg0, kg1, n10, n11, n20, n21);
  k1_gemm64<<<dim3(5, 13, 6), 256>>>(disc_w1, gat_wl, gat_wr, gat_bl, gat_br,
                                     disc_w2, gat_att);
  k235_mega<<<360 + NB*NM, 256>>>(disc_w2, gat_att, gat_bias);
  k2b_decide<<<162, 256>>>(disc_b2);
  k35_softmax<<<37, 256>>>();
  k4_agg<<<78 + 20, 256>>>(gat_bias, out_w, out_b, latent);
  k6_out<<<20, 256>>>(out_w, out_b, latent, out);
}

// round 14
// speedup vs baseline: 1.3283x; 1.3169x over previous
#include <cuda_runtime.h>
#include <cstdint>
#include <math.h>

#define NB 2
#define NC 64
#define NN 144
#define NM 145
#define NL 800
#define NMP 148   // padded alphaT row stride (float4-aligned)

// ---------------- scratch (device globals; no allocation) -------------------
__device__ float g_pos[NB*NN*NC];
__device__ float g_pa[NL];
__device__ float g_nodes_cg[NB*NM*NC];
__device__ float g_nodes_id[NB*NM*NC];
__device__ float g_pi [NB*NN*NL];
__device__ float g_pjp[NB*NN*NL];
__device__ float g_xl_cg[NB*NM*NL];
__device__ float g_xr_cg[NB*NM*NL];
__device__ float g_xl_id[NB*NM*NL];
__device__ float g_xr_id[NB*NM*NL];
__device__ float g_cgT[NB*NN*NN];         // hard sample, TRANSPOSED [b][j][i]
__device__ float g_gum[NB*NN*NN];         // precomputed gumbel0 - gumbel1
__device__ float g_alphaT[NB*NM*NMP];
__device__ float g_agg_cg[NB*NM*NL];
__device__ float g_agg_id[NB*NM*NL];
__device__ float g_y_cg[NB*NM*NC];
__device__ float g_y_id[NB*NM*NC];
__device__ float g_zp[10*2*192*192];      // disc |.| partials [chunk][b][i][j]
__device__ float g_zg[10*2*192*192];      // gat  |.| partials [chunk][b][j][i] (TRANSPOSED)
__device__ float g_ud[NB*NN], g_vd[NB*NN];
__device__ float g_ug[NB*NM], g_vg[NB*NM];
__device__ float g_loss1, g_loss2;
__device__ unsigned int g_cnt6;

// ---------------- threefry2x32 (JAX-exact, partitionable) -------------------
__host__ __device__ __forceinline__ void tf2x32(uint32_t k0, uint32_t k1,
                                                uint32_t x0, uint32_t x1,
                                                uint32_t &o0, uint32_t &o1) {
  uint32_t k2 = k0 ^ k1 ^ 0x1BD11BDAu;
  x0 += k0; x1 += k1;
#define TFR(r) { x0 += x1; x1 = (x1 << (r)) | (x1 >> (32 - (r))); x1 ^= x0; }
  TFR(13) TFR(15) TFR(26) TFR(6)
  x0 += k1; x1 += k2 + 1u;
  TFR(17) TFR(29) TFR(16) TFR(24)
  x0 += k2; x1 += k0 + 2u;
  TFR(13) TFR(15) TFR(26) TFR(6)
  x0 += k0; x1 += k1 + 3u;
  TFR(17) TFR(29) TFR(16) TFR(24)
  x0 += k1; x1 += k2 + 4u;
  TFR(13) TFR(15) TFR(26) TFR(6)
  x0 += k2; x1 += k0 + 5u;
#undef TFR
  o0 = x0; o1 = x1;
}

__device__ __forceinline__ uint32_t jx_bits(uint32_t k0, uint32_t k1, uint32_t f) {
  uint32_t o0, o1; tf2x32(k0, k1, 0u, f, o0, o1); return o0 ^ o1;
}
__device__ __forceinline__ float jx_u01(uint32_t bits) {
  return __uint_as_float((bits >> 9) | 0x3F800000u) - 1.0f;
}
__device__ __forceinline__ float jx_gumbel(uint32_t k0, uint32_t k1, uint32_t f) {
  float u01 = jx_u01(jx_bits(k0, k1, f));
  const float tiny = 1.17549435e-38f;
  float u = fmaxf(tiny, u01 + tiny);
  return -logf(-logf(u));
}
__device__ __forceinline__ float jx_normal(uint32_t k0, uint32_t k1, uint32_t f) {
  float u01 = jx_u01(jx_bits(k0, k1, f));
  const float lo = -0.99999994f;
  float u = fmaxf(lo, u01 * 2.0f + lo);
  return 1.41421356f * erfinvf(u);
}

// ---------------- K0: pos, pa, noisy nodes, gumbel diffs, zero u/v ----------
__global__ void k0_prep(const float* __restrict__ latent,
                        const float* __restrict__ a_dense_b,
                        const float* __restrict__ disc_w1,
                        const float* __restrict__ disc_b1,
                        uint32_t kg0, uint32_t kg1,
                        uint32_t n10, uint32_t n11, uint32_t n20, uint32_t n21) {
  int tid = blockIdx.x * blockDim.x + threadIdx.x;
  if (tid == 0) { g_loss1 = 0.f; g_loss2 = 0.f; g_cnt6 = 0u; }
  const float t = -logf(10000.0f) / 64.0f;
  const int R0 = NB*NN*NC;
  const int R1 = R0 + NL;
  const int R2 = R1 + 2*NB*NM*NC;
  const int R3 = R2 + 2*NB*NN + 2*NB*NM;
  const int R4 = R3 + NB*NN*NN;
  if (tid < R0) {
    int b = tid / (NN*NC), r = tid % (NN*NC);
    int n = r >> 6, c = r & 63;
    int h = n / 12, w = n % 12;
    float lat = latent[((b*NC + c)*12 + h)*12 + w];
    float dv = expf((float)(2*(c >> 1)) * t);
    float ang = (float)n * dv;
    float pe = (c & 1) ? cosf(ang) : sinf(ang);
    g_pos[tid] = lat + pe;
  } else if (tid < R1) {
    int l = tid - R0;
    float s = disc_b1[l];
    #pragma unroll 8
    for (int c = 0; c < NC; c++) s += a_dense_b[c] * disc_w1[(2*NC + c)*NL + l];
    g_pa[l] = s;
  } else if (tid < R2) {
    int q = tid - R1;
    int which = q / (NB*NM*NC);
    int f = q % (NB*NM*NC);
    int b = f / (NM*NC), r = f % (NM*NC);
    int m = r >> 6, c = r & 63;
    float base;
    if (m < NN) {
      int h = m / 12, w = m % 12;
      float lat = latent[((b*NC + c)*12 + h)*12 + w];
      float dv = expf((float)(2*(c >> 1)) * t);
      float ang = (float)m * dv;
      float pe = (c & 1) ? cosf(ang) : sinf(ang);
      base = lat + pe;
    } else {
      base = a_dense_b[c];
    }
    uint32_t k0 = which ? n20 : n10, k1 = which ? n21 : n11;
    float noise = jx_normal(k0, k1, (uint32_t)f);
    (which ? g_nodes_id : g_nodes_cg)[f] = base + noise;
  } else if (tid < R3) {
    int q = tid - R2;
    if (q < NB*NN) g_ud[q] = 0.f;
    else if (q < 2*NB*NN) g_vd[q - NB*NN] = 0.f;
    else if (q < 2*NB*NN + NB*NM) g_ug[q - 2*NB*NN] = 0.f;
    else g_vg[q - 2*NB*NN - NB*NM] = 0.f;
  } else if (tid < R4) {
    int gidx = tid - R3;
    uint32_t f = (uint32_t)(gidx * 2);
    float gg0 = jx_gumbel(kg0, kg1, f);
    float gg1 = jx_gumbel(kg0, kg1, f + 1u);
    g_gum[gidx] = gg0 - gg1;
  }
}

// ---------------- K1: six (rows x 64)@(64 x 800) GEMMs, 64x64 tile, 4x4 -----
__global__ __launch_bounds__(256)
void k1_gemm64(const float* __restrict__ disc_w1,
               const float* __restrict__ gat_wl,
               const float* __restrict__ gat_wr,
               const float* __restrict__ gat_bl,
               const float* __restrict__ gat_br,
               const float* __restrict__ disc_w2,
               const float* __restrict__ gat_att) {
  __shared__ __align__(16) float Ast[64][68];   // [k][row]
  __shared__ __align__(16) float Ws[64][68];    // [k][col]
  const float *A, *W, *bias; float *C; int rows;
  const float *uvw = nullptr; float *uvdst = nullptr;
  switch (blockIdx.z) {
    case 0:  A = g_pos;      W = disc_w1;          bias = nullptr; C = g_pi;    rows = NB*NN;
             uvw = disc_w2; uvdst = g_ud; break;
    case 1:  A = g_pos;      W = disc_w1 + NC*NL;  bias = g_pa;    C = g_pjp;   rows = NB*NN;
             uvw = disc_w2; uvdst = g_vd; break;
    case 2:  A = g_nodes_cg; W = gat_wl;           bias = gat_bl;  C = g_xl_cg; rows = NB*NM;
             uvw = gat_att; uvdst = g_ug; break;
    case 3:  A = g_nodes_cg; W = gat_wr;           bias = gat_br;  C = g_xr_cg; rows = NB*NM;
             uvw = gat_att; uvdst = g_vg; break;
    case 4:  A = g_nodes_id; W = gat_wl;           bias = gat_bl;  C = g_xl_id; rows = NB*NM; break;
    default: A = g_nodes_id; W = gat_wr;           bias = gat_br;  C = g_xr_id; rows = NB*NM; break;
  }
  int r0 = blockIdx.x * 64, c0 = blockIdx.y * 64;
  if (r0 >= rows) return;
  int tid = threadIdx.x;
  int ty = tid >> 4, tx = tid & 15;
  int rr = tid >> 2, g = tid & 3;
  #pragma unroll
  for (int m = 0; m < 4; m++) {
    int k = g*16 + m*4;
    float4 av = make_float4(0.f, 0.f, 0.f, 0.f);
    if (r0 + rr < rows) av = *(const float4*)&A[(r0 + rr)*NC + k];
    Ast[k+0][rr] = av.x; Ast[k+1][rr] = av.y; Ast[k+2][rr] = av.z; Ast[k+3][rr] = av.w;
  }
  #pragma unroll
  for (int u = 0; u < 4; u++) {
    int idx = tid + u*256;
    int k = idx >> 4, c4 = (idx & 15) * 4;
    float4 wv = make_float4(0.f, 0.f, 0.f, 0.f);
    if (c0 + c4 < NL) wv = *(const float4*)&W[k*NL + c0 + c4];
    *(float4*)&Ws[k][c4] = wv;
  }
  __syncthreads();
  float acc[4][4] = {};
  #pragma unroll
  for (int k = 0; k < 64; k++) {
    float4 x = *(const float4*)&Ast[k][4*ty];
    float4 w = *(const float4*)&Ws[k][4*tx];
    float xv[4] = {x.x, x.y, x.z, x.w};
    float wv[4] = {w.x, w.y, w.z, w.w};
    #pragma unroll
    for (int di = 0; di < 4; di++)
      #pragma unroll
      for (int dj = 0; dj < 4; dj++)
        acc[di][dj] = fmaf(xv[di], wv[dj], acc[di][dj]);
  }
  float bb[4], v[4][4];
  #pragma unroll
  for (int dj = 0; dj < 4; dj++) {
    int c = c0 + 4*tx + dj;
    bb[dj] = (bias && c < NL) ? bias[c] : 0.f;
  }
  #pragma unroll
  for (int di = 0; di < 4; di++) {
    int r = r0 + 4*ty + di;
    #pragma unroll
    for (int dj = 0; dj < 4; dj++) v[di][dj] = acc[di][dj] + bb[dj];
    if (r < rows) {
      #pragma unroll
      for (int dj = 0; dj < 4; dj++) {
        int c = c0 + 4*tx + dj;
        if (c < NL) C[r*NL + c] = v[di][dj];
      }
    }
  }
  if (uvdst) {
    float wr[4];
    #pragma unroll
    for (int dj = 0; dj < 4; dj++) {
      int c = c0 + 4*tx + dj;
      wr[dj] = (c < NL) ? uvw[c] : 0.f;
    }
    #pragma unroll
    for (int di = 0; di < 4; di++) {
      float s = wr[0]*v[di][0] + wr[1]*v[di][1] + wr[2]*v[di][2] + wr[3]*v[di][3];
      #pragma unroll
      for (int sh = 8; sh; sh >>= 1) s += __shfl_down_sync(0xffffffffu, s, sh, 16);
      int r = r0 + 4*ty + di;
      if (tx == 0 && r < rows) atomicAdd(&uvdst[r], s);
    }
  }
}

// ---------------- K235: pairwise |.| (disc [i][j], gat TRANSPOSED [j][i]) ---
__global__ __launch_bounds__(256)
void k235_mega(const float* __restrict__ disc_w2,
               const float* __restrict__ gat_att,
               const float* __restrict__ gat_bias) {
  __shared__ __align__(16) float sm[2*16*68 + 32];
  int bid = blockIdx.x;
  int tid = threadIdx.x;
  if (bid < 360) {
    int which = bid / 180; int rem = bid % 180;
    int b = rem / 90; rem %= 90;
    int chunk = rem / 9; int t9 = rem % 9;
    int r0t = (t9 / 3) * 64, c0t = (t9 % 3) * 64;
    float (*Pt)[68] = (float(*)[68])sm;
    float (*Qt)[68] = (float(*)[68])(sm + 16*68);
    float* ws = sm + 2*16*68;
    const float *pr, *pc, *wsg; int nrows; float* zout;
    if (which == 0) {
      // disc: rows = i (from pi), cols = j (from pjp) -> zp[i][j]
      pr = g_pi  + b*NN*NL; pc = g_pjp + b*NN*NL; wsg = disc_w2; nrows = NN;
      zout = g_zp + (chunk*2 + b)*192*192;
    } else {
      // gat: rows = j (from xr), cols = i (from xl) -> zg[j][i]  (TRANSPOSED)
      pr = g_xr_cg + b*NM*NL; pc = g_xl_cg + b*NM*NL; wsg = gat_att; nrows = NM;
      zout = g_zg + (chunk*2 + b)*192*192;
    }
    int ty = tid >> 4, tx = tid & 15;
    int rr = tid >> 2, g = tid & 3;
    float acc[4][4] = {};
    for (int step = 0; step < 5; step++) {
      int lbase = chunk*80 + step*16;
      float4 pv = make_float4(0.f,0.f,0.f,0.f), qv = pv;
      if (r0t + rr < nrows) pv = *(const float4*)&pr[(r0t + rr)*NL + lbase + g*4];
      if (c0t + rr < nrows) qv = *(const float4*)&pc[(c0t + rr)*NL + lbase + g*4];
      float wreg = (tid < 16) ? wsg[lbase + tid] : 0.f;
      __syncthreads();
      int kb = g*4;
      Pt[kb+0][rr] = pv.x; Pt[kb+1][rr] = pv.y; Pt[kb+2][rr] = pv.z; Pt[kb+3][rr] = pv.w;
      Qt[kb+0][rr] = qv.x; Qt[kb+1][rr] = qv.y; Qt[kb+2][rr] = qv.z; Qt[kb+3][rr] = qv.w;
      if (tid < 16) ws[tid] = wreg;
      __syncthreads();
      #pragma unroll
      for (int k = 0; k < 16; k++) {
        float a = ws[k];
        float4 p = *(const float4*)&Pt[k][4*ty];
        float4 q = *(const float4*)&Qt[k][4*tx];
        float pvv[4] = {p.x, p.y, p.z, p.w};
        float qvv[4] = {q.x, q.y, q.z, q.w};
        #pragma unroll
        for (int di = 0; di < 4; di++)
          #pragma unroll
          for (int dj = 0; dj < 4; dj++)
            acc[di][dj] = fmaf(a, fabsf(pvv[di] + qvv[dj]), acc[di][dj]);
      }
    }
    #pragma unroll
    for (int di = 0; di < 4; di++) {
      int r = r0t + 4*ty + di;
      float4 o = make_float4(acc[di][0], acc[di][1], acc[di][2], acc[di][3]);
      *(float4*)&zout[r*192 + c0t + 4*tx] = o;
    }
  } else {
    // ---- identity-graph transitioner ----
    int q = bid - 360;
    int b = q / NM, j = q % NM;
    float* es   = sm;
    float* red  = sm + 160;
    float* abuf = sm + 416;
    const float* xl = g_xl_id + b*NM*NL;
    const float* xr = g_xr_id + b*NM*NL;
    float* outp = g_agg_id + b*NM*NL;
    if (j < NN) {
      float s1 = 0.f, s2 = 0.f;
      for (int l = tid; l < NL; l += 256) {
        float xrv = xr[j*NL + l];
        float a = gat_att[l];
        float t1 = xl[j*NL + l] + xrv;
        s1 += a * fmaxf(t1, 0.2f * t1);
        float t2 = xl[NN*NL + l] + xrv;
        s2 += a * fmaxf(t2, 0.2f * t2);
      }
      red[tid] = s1; __syncthreads();
      for (int s = 128; s; s >>= 1) { if (tid < s) red[tid] += red[tid + s]; __syncthreads(); }
      float e1 = red[0]; __syncthreads();
      red[tid] = s2; __syncthreads();
      for (int s = 128; s; s >>= 1) { if (tid < s) red[tid] += red[tid + s]; __syncthreads(); }
      float e2 = red[0];
      float m = fmaxf(e1, e2);
      float x1 = expf(e1 - m), x2 = expf(e2 - m);
      float inv = 1.0f / (x1 + x2);
      float al1 = x1 * inv, al2 = x2 * inv;
      for (int l = tid; l < NL; l += 256) {
        float v = al1 * xl[j*NL + l] + al2 * xl[NN*NL + l] + gat_bias[l];
        outp[j*NL + l] = fmaxf(v, 0.f);
      }
    } else {
      int wid = tid >> 5, lane = tid & 31;
      for (int i = wid; i < NM; i += 8) {
        float s = 0.f;
        for (int l = lane; l < NL; l += 32) {
          float t = xl[i*NL + l] + xr[NN*NL + l];
          s += gat_att[l] * fmaxf(t, 0.2f * t);
        }
        for (int sh = 16; sh; sh >>= 1) s += __shfl_xor_sync(0xffffffffu, s, sh);
        if (lane == 0) es[i] = s;
      }
      __syncthreads();
      if (tid == 0) {
        float m = -3.4e38f;
        for (int i = 0; i < NM; i++) m = fmaxf(m, es[i]);
        float sum = 0.f;
        for (int i = 0; i < NM; i++) sum += expf(es[i] - m);
        abuf[0] = m; abuf[1] = 1.0f / sum;
      }
      __syncthreads();
      float m = abuf[0], inv = abuf[1];
      for (int i = tid; i < NM; i += 256) es[i] = expf(es[i] - m) * inv;
      __syncthreads();
      for (int l = tid; l < NL; l += 256) {
        float acc = gat_bias[l];
        for (int i = 0; i < NM; i++) acc += es[i] * xl[i*NL + l];
        outp[NN*NL + l] = fmaxf(acc, 0.f);
      }
    }
  }
}

// ---------------- K2b: combine -> compare vs gumbel diff + loss1 ------------
__global__ void k2b_decide(const float* __restrict__ disc_b2) {
  __shared__ float red[256];
  int tid = threadIdx.x;
  int gidx = blockIdx.x * 256 + tid;
  float lp = 0.f;
  if (gidx < NB*NN*NN) {
    int b = gidx / (NN*NN), r = gidx % (NN*NN);
    int i = r / NN, j = r % NN;
    float S = 0.f;
    #pragma unroll
    for (int cc = 0; cc < 10; cc++) S += g_zp[((cc*2 + b)*192 + i)*192 + j];
    float z = 0.495f*S + 0.505f*(g_ud[b*NN + i] + g_vd[b*NN + j]) + disc_b2[0];
    float cgv = (z > g_gum[gidx]) ? 1.0f : 0.0f;
    g_cgT[(b*NN + j)*NN + i] = cgv;     // transposed store (scattered, ok)
    float d = (i == j) ? (1.0f - cgv) : cgv;
    lp = d * d;
  }
  red[tid] = lp; __syncthreads();
  for (int s = 128; s; s >>= 1) { if (tid < s) red[tid] += red[tid + s]; __syncthreads(); }
  if (tid == 0) atomicAdd(&g_loss1, red[0]);
}

// ---------------- K35: mask + column softmax (coalesced zg[j][i]) -----------
__global__ void k35_softmax() {
  int warp = (blockIdx.x * blockDim.x + threadIdx.x) >> 5;
  int lane = threadIdx.x & 31;
  if (warp >= NB*NM) return;
  int b = warp / NM, j = warp % NM;
  float vgj = g_vg[b*NM + j];
  float ev[5];
  #pragma unroll
  for (int t = 0; t < 5; t++) {
    int i = lane + 32*t;
    float v = -3.4e38f;
    if (i < NM) {
      bool mask = (i == NN) || (j == NN) || (i == j);
      if (!mask) mask = g_cgT[(b*NN + j)*NN + i] != 0.0f;   // coalesced
      if (mask) {
        float S = 0.f;
        #pragma unroll
        for (int cc = 0; cc < 10; cc++) S += g_zg[((cc*2 + b)*192 + j)*192 + i];  // coalesced
        v = 0.6f*(g_ug[b*NM + i] + vgj) + 0.4f*S;
      } else v = -1e30f;
    }
    ev[t] = v;
  }
  float m = -3.4e38f;
  #pragma unroll
  for (int t = 0; t < 5; t++) m = fmaxf(m, ev[t]);
  #pragma unroll
  for (int s = 16; s; s >>= 1) m = fmaxf(m, __shfl_xor_sync(0xffffffffu, m, s));
  float sum = 0.f;
  #pragma unroll
  for (int t = 0; t < 5; t++) { ev[t] = (ev[t] > -3.0e38f) ? expf(ev[t] - m) : 0.f; sum += ev[t]; }
  #pragma unroll
  for (int s = 16; s; s >>= 1) sum += __shfl_xor_sync(0xffffffffu, sum, s);
  float inv = 1.0f / sum;
  float* aT = g_alphaT + (b*NM + j)*NMP;
  #pragma unroll
  for (int t = 0; t < 5; t++) {
    int i = lane + 32*t;
    if (i < NM) aT[i] = ev[t] * inv;
    else if (i < NMP) aT[i] = 0.f;
  }
}

// ---------------- K4: agg_cg, 64x64 tile, 4x4 (pure stage) ------------------
__global__ __launch_bounds__(256)
void k4_aggcg(const float* __restrict__ gat_bias) {
  __shared__ __align__(16) float ATs[16][68];
  __shared__ __align__(16) float Xs[16][68];
  int b = blockIdx.z;
  int j0 = blockIdx.x * 64, l0 = blockIdx.y * 64;
  int tid = threadIdx.x;
  int ty = tid >> 4, tx = tid & 15;
  int rr = tid >> 2, g = tid & 3;
  const float* aT = g_alphaT + b*NM*NMP;
  const float* xl = g_xl_cg + b*NM*NL;
  float acc[4][4] = {};
  for (int step = 0; step < 9; step++) {
    int ib = step*16;
    float4 av = make_float4(0.f,0.f,0.f,0.f);
    if (j0 + rr < NM) av = *(const float4*)&aT[(j0 + rr)*NMP + ib + g*4];
    int fi = tid >> 4, c4 = (tid & 15) * 4;
    float4 xv = make_float4(0.f,0.f,0.f,0.f);
    if (l0 + c4 < NL) xv = *(const float4*)&xl[(ib + fi)*NL + l0 + c4];
    __syncthreads();
    int kb = g*4;
    ATs[kb+0][rr] = av.x; ATs[kb+1][rr] = av.y; ATs[kb+2][rr] = av.z; ATs[kb+3][rr] = av.w;
    *(float4*)&Xs[fi][c4] = xv;
    __syncthreads();
    #pragma unroll
    for (int k = 0; k < 16; k++) {
      float4 a4 = *(const float4*)&ATs[k][4*ty];
      float4 x4 = *(const float4*)&Xs[k][4*tx];
      float avv[4] = {a4.x, a4.y, a4.z, a4.w};
      float xvv[4] = {x4.x, x4.y, x4.z, x4.w};
      #pragma unroll
      for (int di = 0; di < 4; di++)
        #pragma unroll
        for (int dj = 0; dj < 4; dj++)
          acc[di][dj] = fmaf(avv[di], xvv[dj], acc[di][dj]);
    }
  }
  {
    float a144[4], x144[4];
    #pragma unroll
    for (int di = 0; di < 4; di++) {
      int j = j0 + 4*ty + di;
      a144[di] = (j < NM) ? aT[j*NMP + 144] : 0.f;
    }
    #pragma unroll
    for (int dj = 0; dj < 4; dj++) {
      int l = l0 + 4*tx + dj;
      x144[dj] = (l < NL) ? xl[144*NL + l] : 0.f;
    }
    #pragma unroll
    for (int di = 0; di < 4; di++)
      #pragma unroll
      for (int dj = 0; dj < 4; dj++)
        acc[di][dj] = fmaf(a144[di], x144[dj], acc[di][dj]);
  }
  float* outp = g_agg_cg + b*NM*NL;
  #pragma unroll
  for (int di = 0; di < 4; di++) {
    int j = j0 + 4*ty + di;
    if (j < NM) {
      #pragma unroll
      for (int dj = 0; dj < 4; dj++) {
        int l = l0 + 4*tx + dj;
        if (l < NL) outp[j*NL + l] = fmaxf(acc[di][dj] + gat_bias[l], 0.f);
      }
    }
  }
}

// ---------------- K6: dual projection: id->loss2, cg->d_out, scalar ---------
__global__ void k6_out(const float* __restrict__ out_w,
                       const float* __restrict__ out_b,
                       const float* __restrict__ latent,
                       float* __restrict__ d_out) {
  __shared__ __align__(16) float sm[2*32*34 + 256];
  float (*As2)[34] = (float(*)[34])sm;
  float (*Ws)[34]  = (float(*)[34])(sm + 32*34);
  float* red = sm + 2*32*34;
  int bid = blockIdx.x;
  int mode = bid / 20;            // 0 = id (loss2), 1 = cg (write out)
  int q = bid % 20;
  int r0 = (q / 2) * 32, c0 = (q % 2) * 32;
  const float* A = mode ? g_agg_cg : g_agg_id;
  int tid = threadIdx.x, ty = tid >> 4, tx = tid & 15;
  float a00 = 0.f, a01 = 0.f, a10 = 0.f, a11 = 0.f;
  for (int k0 = 0; k0 < NL; k0 += 32) {
    for (int idx = tid; idx < 1024; idx += 256) {
      int r = idx >> 5, c = idx & 31;
      As2[c][r] = (r0 + r < NB*NM) ? A[(r0 + r)*NL + k0 + c] : 0.f;
      Ws[r][c]  = out_w[(k0 + r)*NC + c0 + c];
    }
    __syncthreads();
    #pragma unroll
    for (int k = 0; k < 32; k++) {
      float2 ar = *(const float2*)&As2[k][2*ty];
      float2 w  = *(const float2*)&Ws[k][2*tx];
      a00 = fmaf(ar.x, w.x, a00); a01 = fmaf(ar.x, w.y, a01);
      a10 = fmaf(ar.y, w.x, a10); a11 = fmaf(ar.y, w.y, a11);
    }
    __syncthreads();
  }
  float y[2][2] = {{a00 + out_b[c0 + 2*tx], a01 + out_b[c0 + 2*tx + 1]},
                   {a10 + out_b[c0 + 2*tx], a11 + out_b[c0 + 2*tx + 1]}};
  float lp = 0.f;
  #pragma unroll
  for (int di = 0; di < 2; di++) {
    int r = r0 + 2*ty + di;
    if (r < NB*NM) {
      int b = r / NM, n = r % NM;
      if (n < NN) {
        #pragma unroll
        for (int dj = 0; dj < 2; dj++) {
          int c = c0 + 2*tx + dj;
          int oidx = (b*NC + c)*NN + n;
          if (mode == 1) d_out[oidx] = y[di][dj];
          else { float d = latent[oidx] - y[di][dj]; lp += d*d; }
        }
      }
    }
  }
  if (mode == 0) {
    red[tid] = lp; __syncthreads();
    for (int s = 128; s; s >>= 1) { if (tid < s) red[tid] += red[tid + s]; __syncthreads(); }
    if (tid == 0) atomicAdd(&g_loss2, red[0]);
    __syncthreads();
  }
  if (tid == 0) {
    __threadfence();
    unsigned int old = atomicAdd(&g_cnt6, 1u);
    if (old == gridDim.x - 1) {
      float L2 = atomicAdd(&g_loss2, 0.f);
      float L1 = atomicAdd(&g_loss1, 0.f);
      d_out[NB*NN*NC] = L1 / (float)(NB*NN*NN) + L2 / (float)(NB*NN*NC);
    }
  }
}

// ---------------- launch ----------------------------------------------------
extern "C" void kernel_launch(void* const* d_in, const int* in_sizes, int n_in,
                              void* d_out, int out_size) {
  (void)in_sizes; (void)n_in; (void)out_size;
  const float* latent    = (const float*)d_in[0];
  const float* a_dense_b = (const float*)d_in[2];
  const float* disc_w1   = (const float*)d_in[3];
  const float* disc_b1   = (const float*)d_in[4];
  const float* disc_w2   = (const float*)d_in[5];
  const float* disc_b2   = (const float*)d_in[6];
  const float* gat_wl    = (const float*)d_in[7];
  const float* gat_bl    = (const float*)d_in[8];
  const float* gat_wr    = (const float*)d_in[9];
  const float* gat_br    = (const float*)d_in[10];
  const float* gat_att   = (const float*)d_in[11];
  const float* gat_bias  = (const float*)d_in[12];
  const float* out_w     = (const float*)d_in[13];
  const float* out_b     = (const float*)d_in[14];
  float* out = (float*)d_out;

  uint32_t kg0, kg1, n10, n11, n20, n21, a, b;
  tf2x32(0u, 42u, 0u, 0u, a, b); kg0 = a; kg1 = b;
  tf2x32(0u, 42u, 0u, 1u, a, b); n10 = a; n11 = b;
  tf2x32(0u, 42u, 0u, 2u, a, b); n20 = a; n21 = b;

  int k0_threads = NB*NN*NC + NL + 2*NB*NM*NC + 2*NB*NN + 2*NB*NM + NB*NN*NN;
  k0_prep<<<(k0_threads + 255)/256, 256>>>(latent, a_dense_b, disc_w1, disc_b1,
                                           kg0, kg1, n10, n11, n20, n21);
  k1_gemm64<<<dim3(5, 13, 6), 256>>>(disc_w1, gat_wl, gat_wr, gat_bl, gat_br,
                                     disc_w2, gat_att);
  k235_mega<<<360 + NB*NM, 256>>>(disc_w2, gat_att, gat_bias);
  k2b_decide<<<162, 256>>>(disc_b2);
  k35_softmax<<<37, 256>>>();
  k4_aggcg<<<dim3(3, 13, 2), 256>>>(gat_bias);
  k6_out<<<40, 256>>>(out_w, out_b, latent, out);
}

// round 15
// speedup vs baseline: 1.6474x; 1.2402x over previous
#include <cuda_runtime.h>
#include <cstdint>
#include <math.h>

#define NB 2
#define NC 64
#define NN 144
#define NM 145
#define NL 800
#define NMP 148   // padded alphaT row stride (float4-aligned)

// ---------------- scratch (device globals; no allocation) -------------------
__device__ float g_pos[NB*NN*NC];
__device__ float g_pa[NL];
__device__ float g_nodes_cg[NB*NM*NC];
__device__ float g_nodes_id[NB*NM*NC];
__device__ float g_pi [NB*NN*NL];
__device__ float g_pjp[NB*NN*NL];
__device__ float g_xl_cg[NB*NM*NL];
__device__ float g_xr_cg[NB*NM*NL];
__device__ float g_xl_id[NB*NM*NL];
__device__ float g_xr_id[NB*NM*NL];
__device__ float g_cgT[NB*NN*NN];         // hard sample, TRANSPOSED [b][j][i]
__device__ float g_alphaT[NB*NM*NMP];
__device__ float g_agg_cg[NB*NM*NL];
__device__ float g_agg_id[NB*NM*NL];
__device__ float g_zp[10*2*192*192];      // disc |.| partials [chunk][b][i][j]
__device__ float g_zg[10*2*192*192];      // gat  |.| partials [chunk][b][j][i] (TRANSPOSED)
__device__ float g_ud[NB*NN], g_vd[NB*NN];
__device__ float g_ug[NB*NM], g_vg[NB*NM];
__device__ float g_loss1, g_loss2;
__device__ unsigned int g_cnt6;

// ---------------- threefry2x32 (JAX-exact, partitionable) -------------------
__host__ __device__ __forceinline__ void tf2x32(uint32_t k0, uint32_t k1,
                                                uint32_t x0, uint32_t x1,
                                                uint32_t &o0, uint32_t &o1) {
  uint32_t k2 = k0 ^ k1 ^ 0x1BD11BDAu;
  x0 += k0; x1 += k1;
#define TFR(r) { x0 += x1; x1 = (x1 << (r)) | (x1 >> (32 - (r))); x1 ^= x0; }
  TFR(13) TFR(15) TFR(26) TFR(6)
  x0 += k1; x1 += k2 + 1u;
  TFR(17) TFR(29) TFR(16) TFR(24)
  x0 += k2; x1 += k0 + 2u;
  TFR(13) TFR(15) TFR(26) TFR(6)
  x0 += k0; x1 += k1 + 3u;
  TFR(17) TFR(29) TFR(16) TFR(24)
  x0 += k1; x1 += k2 + 4u;
  TFR(13) TFR(15) TFR(26) TFR(6)
  x0 += k2; x1 += k0 + 5u;
#undef TFR
  o0 = x0; o1 = x1;
}

__device__ __forceinline__ uint32_t jx_bits(uint32_t k0, uint32_t k1, uint32_t f) {
  uint32_t o0, o1; tf2x32(k0, k1, 0u, f, o0, o1); return o0 ^ o1;
}
__device__ __forceinline__ float jx_u01(uint32_t bits) {
  return __uint_as_float((bits >> 9) | 0x3F800000u) - 1.0f;
}
__device__ __forceinline__ float jx_gumbel(uint32_t k0, uint32_t k1, uint32_t f) {
  float u01 = jx_u01(jx_bits(k0, k1, f));
  const float tiny = 1.17549435e-38f;
  float u = fmaxf(tiny, u01 + tiny);
  return -logf(-logf(u));
}
__device__ __forceinline__ float jx_normal(uint32_t k0, uint32_t k1, uint32_t f) {
  float u01 = jx_u01(jx_bits(k0, k1, f));
  const float lo = -0.99999994f;
  float u = fmaxf(lo, u01 * 2.0f + lo);
  return 1.41421356f * erfinvf(u);
}

// ---------------- K0: pos, pa, noisy nodes, zero u/v ------------------------
__global__ void k0_prep(const float* __restrict__ latent,
                        const float* __restrict__ a_dense_b,
                        const float* __restrict__ disc_w1,
                        const float* __restrict__ disc_b1,
                        uint32_t n10, uint32_t n11, uint32_t n20, uint32_t n21) {
  int tid = blockIdx.x * blockDim.x + threadIdx.x;
  if (tid == 0) { g_loss1 = 0.f; g_loss2 = 0.f; g_cnt6 = 0u; }
  const float t = -logf(10000.0f) / 64.0f;
  const int R0 = NB*NN*NC;
  const int R1 = R0 + NL;
  const int R2 = R1 + 2*NB*NM*NC;
  const int R3 = R2 + 2*NB*NN + 2*NB*NM;
  if (tid < R0) {
    int b = tid / (NN*NC), r = tid % (NN*NC);
    int n = r >> 6, c = r & 63;
    int h = n / 12, w = n % 12;
    float lat = latent[((b*NC + c)*12 + h)*12 + w];
    float dv = expf((float)(2*(c >> 1)) * t);
    float ang = (float)n * dv;
    float pe = (c & 1) ? cosf(ang) : sinf(ang);
    g_pos[tid] = lat + pe;
  } else if (tid < R1) {
    int l = tid - R0;
    float s = disc_b1[l];
    #pragma unroll 8
    for (int c = 0; c < NC; c++) s += a_dense_b[c] * disc_w1[(2*NC + c)*NL + l];
    g_pa[l] = s;
  } else if (tid < R2) {
    int q = tid - R1;
    int which = q / (NB*NM*NC);
    int f = q % (NB*NM*NC);
    int b = f / (NM*NC), r = f % (NM*NC);
    int m = r >> 6, c = r & 63;
    float base;
    if (m < NN) {
      int h = m / 12, w = m % 12;
      float lat = latent[((b*NC + c)*12 + h)*12 + w];
      float dv = expf((float)(2*(c >> 1)) * t);
      float ang = (float)m * dv;
      float pe = (c & 1) ? cosf(ang) : sinf(ang);
      base = lat + pe;
    } else {
      base = a_dense_b[c];
    }
    uint32_t k0 = which ? n20 : n10, k1 = which ? n21 : n11;
    float noise = jx_normal(k0, k1, (uint32_t)f);
    (which ? g_nodes_id : g_nodes_cg)[f] = base + noise;
  } else if (tid < R3) {
    int q = tid - R2;
    if (q < NB*NN) g_ud[q] = 0.f;
    else if (q < 2*NB*NN) g_vd[q - NB*NN] = 0.f;
    else if (q < 2*NB*NN + NB*NM) g_ug[q - 2*NB*NN] = 0.f;
    else g_vg[q - 2*NB*NN - NB*NM] = 0.f;
  }
}

// ---------------- K1: six (rows x 64)@(64 x 800) GEMMs, 64x64 tile, 4x4 -----
__global__ __launch_bounds__(256)
void k1_gemm64(const float* __restrict__ disc_w1,
               const float* __restrict__ gat_wl,
               const float* __restrict__ gat_wr,
               const float* __restrict__ gat_bl,
               const float* __restrict__ gat_br,
               const float* __restrict__ disc_w2,
               const float* __restrict__ gat_att) {
  __shared__ __align__(16) float Ast[64][68];   // [k][row]
  __shared__ __align__(16) float Ws[64][68];    // [k][col]
  const float *A, *W, *bias; float *C; int rows;
  const float *uvw = nullptr; float *uvdst = nullptr;
  switch (blockIdx.z) {
    case 0:  A = g_pos;      W = disc_w1;          bias = nullptr; C = g_pi;    rows = NB*NN;
             uvw = disc_w2; uvdst = g_ud; break;
    case 1:  A = g_pos;      W = disc_w1 + NC*NL;  bias = g_pa;    C = g_pjp;   rows = NB*NN;
             uvw = disc_w2; uvdst = g_vd; break;
    case 2:  A = g_nodes_cg; W = gat_wl;           bias = gat_bl;  C = g_xl_cg; rows = NB*NM;
             uvw = gat_att; uvdst = g_ug; break;
    case 3:  A = g_nodes_cg; W = gat_wr;           bias = gat_br;  C = g_xr_cg; rows = NB*NM;
             uvw = gat_att; uvdst = g_vg; break;
    case 4:  A = g_nodes_id; W = gat_wl;           bias = gat_bl;  C = g_xl_id; rows = NB*NM; break;
    default: A = g_nodes_id; W = gat_wr;           bias = gat_br;  C = g_xr_id; rows = NB*NM; break;
  }
  int r0 = blockIdx.x * 64, c0 = blockIdx.y * 64;
  if (r0 >= rows) return;
  int tid = threadIdx.x;
  int ty = tid >> 4, tx = tid & 15;
  int rr = tid >> 2, g = tid & 3;
  #pragma unroll
  for (int m = 0; m < 4; m++) {
    int k = g*16 + m*4;
    float4 av = make_float4(0.f, 0.f, 0.f, 0.f);
    if (r0 + rr < rows) av = *(const float4*)&A[(r0 + rr)*NC + k];
    Ast[k+0][rr] = av.x; Ast[k+1][rr] = av.y; Ast[k+2][rr] = av.z; Ast[k+3][rr] = av.w;
  }
  #pragma unroll
  for (int u = 0; u < 4; u++) {
    int idx = tid + u*256;
    int k = idx >> 4, c4 = (idx & 15) * 4;
    float4 wv = make_float4(0.f, 0.f, 0.f, 0.f);
    if (c0 + c4 < NL) wv = *(const float4*)&W[k*NL + c0 + c4];
    *(float4*)&Ws[k][c4] = wv;
  }
  __syncthreads();
  float acc[4][4] = {};
  #pragma unroll
  for (int k = 0; k < 64; k++) {
    float4 x = *(const float4*)&Ast[k][4*ty];
    float4 w = *(const float4*)&Ws[k][4*tx];
    float xv[4] = {x.x, x.y, x.z, x.w};
    float wv[4] = {w.x, w.y, w.z, w.w};
    #pragma unroll
    for (int di = 0; di < 4; di++)
      #pragma unroll
      for (int dj = 0; dj < 4; dj++)
        acc[di][dj] = fmaf(xv[di], wv[dj], acc[di][dj]);
  }
  float bb[4], v[4][4];
  #pragma unroll
  for (int dj = 0; dj < 4; dj++) {
    int c = c0 + 4*tx + dj;
    bb[dj] = (bias && c < NL) ? bias[c] : 0.f;
  }
  #pragma unroll
  for (int di = 0; di < 4; di++) {
    int r = r0 + 4*ty + di;
    #pragma unroll
    for (int dj = 0; dj < 4; dj++) v[di][dj] = acc[di][dj] + bb[dj];
    if (r < rows) {
      #pragma unroll
      for (int dj = 0; dj < 4; dj++) {
        int c = c0 + 4*tx + dj;
        if (c < NL) C[r*NL + c] = v[di][dj];
      }
    }
  }
  if (uvdst) {
    float wr[4];
    #pragma unroll
    for (int dj = 0; dj < 4; dj++) {
      int c = c0 + 4*tx + dj;
      wr[dj] = (c < NL) ? uvw[c] : 0.f;
    }
    #pragma unroll
    for (int di = 0; di < 4; di++) {
      float s = wr[0]*v[di][0] + wr[1]*v[di][1] + wr[2]*v[di][2] + wr[3]*v[di][3];
      #pragma unroll
      for (int sh = 8; sh; sh >>= 1) s += __shfl_down_sync(0xffffffffu, s, sh, 16);
      int r = r0 + 4*ty + di;
      if (tx == 0 && r < rows) atomicAdd(&uvdst[r], s);
    }
  }
}

// ---------------- K235: pairwise |.| (disc [i][j], gat [j][i]) + id (j<NN) --
__global__ __launch_bounds__(256)
void k235_mega(const float* __restrict__ disc_w2,
               const float* __restrict__ gat_att,
               const float* __restrict__ gat_bias) {
  __shared__ __align__(16) float sm[2*16*68 + 32];
  int bid = blockIdx.x;
  int tid = threadIdx.x;
  if (bid < 360) {
    int which = bid / 180; int rem = bid % 180;
    int b = rem / 90; rem %= 90;
    int chunk = rem / 9; int t9 = rem % 9;
    int r0t = (t9 / 3) * 64, c0t = (t9 % 3) * 64;
    float (*Pt)[68] = (float(*)[68])sm;
    float (*Qt)[68] = (float(*)[68])(sm + 16*68);
    float* ws = sm + 2*16*68;
    const float *pr, *pc, *wsg; int nrows; float* zout;
    if (which == 0) {
      pr = g_pi  + b*NN*NL; pc = g_pjp + b*NN*NL; wsg = disc_w2; nrows = NN;
      zout = g_zp + (chunk*2 + b)*192*192;
    } else {
      pr = g_xr_cg + b*NM*NL; pc = g_xl_cg + b*NM*NL; wsg = gat_att; nrows = NM;
      zout = g_zg + (chunk*2 + b)*192*192;
    }
    int ty = tid >> 4, tx = tid & 15;
    int rr = tid >> 2, g = tid & 3;
    float acc[4][4] = {};
    for (int step = 0; step < 5; step++) {
      int lbase = chunk*80 + step*16;
      float4 pv = make_float4(0.f,0.f,0.f,0.f), qv = pv;
      if (r0t + rr < nrows) pv = *(const float4*)&pr[(r0t + rr)*NL + lbase + g*4];
      if (c0t + rr < nrows) qv = *(const float4*)&pc[(c0t + rr)*NL + lbase + g*4];
      float wreg = (tid < 16) ? wsg[lbase + tid] : 0.f;
      __syncthreads();
      int kb = g*4;
      Pt[kb+0][rr] = pv.x; Pt[kb+1][rr] = pv.y; Pt[kb+2][rr] = pv.z; Pt[kb+3][rr] = pv.w;
      Qt[kb+0][rr] = qv.x; Qt[kb+1][rr] = qv.y; Qt[kb+2][rr] = qv.z; Qt[kb+3][rr] = qv.w;
      if (tid < 16) ws[tid] = wreg;
      __syncthreads();
      #pragma unroll
      for (int k = 0; k < 16; k++) {
        float a = ws[k];
        float4 p = *(const float4*)&Pt[k][4*ty];
        float4 q = *(const float4*)&Qt[k][4*tx];
        float pvv[4] = {p.x, p.y, p.z, p.w};
        float qvv[4] = {q.x, q.y, q.z, q.w};
        #pragma unroll
        for (int di = 0; di < 4; di++)
          #pragma unroll
          for (int dj = 0; dj < 4; dj++)
            acc[di][dj] = fmaf(a, fabsf(pvv[di] + qvv[dj]), acc[di][dj]);
      }
    }
    #pragma unroll
    for (int di = 0; di < 4; di++) {
      int r = r0t + 4*ty + di;
      float4 o = make_float4(acc[di][0], acc[di][1], acc[di][2], acc[di][3]);
      *(float4*)&zout[r*192 + c0t + 4*tx] = o;
    }
  } else {
    // ---- identity-graph transitioner: only j < NN output rows are live ----
    int q = bid - 360;
    int b = q / NN, j = q % NN;
    float* red = sm;
    const float* xl = g_xl_id + b*NM*NL;
    const float* xr = g_xr_id + b*NM*NL;
    float* outp = g_agg_id + b*NM*NL;
    float s1 = 0.f, s2 = 0.f;
    for (int l = tid; l < NL; l += 256) {
      float xrv = xr[j*NL + l];
      float a = gat_att[l];
      float t1 = xl[j*NL + l] + xrv;
      s1 += a * fmaxf(t1, 0.2f * t1);
      float t2 = xl[NN*NL + l] + xrv;
      s2 += a * fmaxf(t2, 0.2f * t2);
    }
    red[tid] = s1; __syncthreads();
    for (int s = 128; s; s >>= 1) { if (tid < s) red[tid] += red[tid + s]; __syncthreads(); }
    float e1 = red[0]; __syncthreads();
    red[tid] = s2; __syncthreads();
    for (int s = 128; s; s >>= 1) { if (tid < s) red[tid] += red[tid + s]; __syncthreads(); }
    float e2 = red[0];
    float m = fmaxf(e1, e2);
    float x1 = expf(e1 - m), x2 = expf(e2 - m);
    float inv = 1.0f / (x1 + x2);
    float al1 = x1 * inv, al2 = x2 * inv;
    for (int l = tid; l < NL; l += 256) {
      float v = al1 * xl[j*NL + l] + al2 * xl[NN*NL + l] + gat_bias[l];
      outp[j*NL + l] = fmaxf(v, 0.f);
    }
  }
}

// ---------------- K2b: combine -> inline gumbel decide + loss1 --------------
__global__ void k2b_decide(const float* __restrict__ disc_b2,
                           uint32_t kg0, uint32_t kg1) {
  __shared__ float red[256];
  int tid = threadIdx.x;
  int gidx = blockIdx.x * 256 + tid;
  float lp = 0.f;
  if (gidx < NB*NN*NN) {
    int b = gidx / (NN*NN), r = gidx % (NN*NN);
    int i = r / NN, j = r % NN;
    float S = 0.f;
    #pragma unroll
    for (int cc = 0; cc < 10; cc++) S += g_zp[((cc*2 + b)*192 + i)*192 + j];
    uint32_t f = (uint32_t)(gidx * 2);
    float gd = jx_gumbel(kg0, kg1, f) - jx_gumbel(kg0, kg1, f + 1u);
    float z = 0.495f*S + 0.505f*(g_ud[b*NN + i] + g_vd[b*NN + j]) + disc_b2[0];
    float cgv = (z > gd) ? 1.0f : 0.0f;
    g_cgT[(b*NN + j)*NN + i] = cgv;     // transposed store (scattered, ok)
    float d = (i == j) ? (1.0f - cgv) : cgv;
    lp = d * d;
  }
  red[tid] = lp; __syncthreads();
  for (int s = 128; s; s >>= 1) { if (tid < s) red[tid] += red[tid + s]; __syncthreads(); }
  if (tid == 0) atomicAdd(&g_loss1, red[0]);
}

// ---------------- K35: mask + column softmax (coalesced zg[j][i]) -----------
__global__ void k35_softmax() {
  int warp = (blockIdx.x * blockDim.x + threadIdx.x) >> 5;
  int lane = threadIdx.x & 31;
  if (warp >= NB*NM) return;
  int b = warp / NM, j = warp % NM;
  if (j == NN) return;                  // dead output row (sliced off)
  float vgj = g_vg[b*NM + j];
  float ev[5];
  #pragma unroll
  for (int t = 0; t < 5; t++) {
    int i = lane + 32*t;
    float v = -3.4e38f;
    if (i < NM) {
      bool mask = (i == NN) || (i == j);
      if (!mask) mask = g_cgT[(b*NN + j)*NN + i] != 0.0f;   // coalesced
      if (mask) {
        float S = 0.f;
        #pragma unroll
        for (int cc = 0; cc < 10; cc++) S += g_zg[((cc*2 + b)*192 + j)*192 + i];  // coalesced
        v = 0.6f*(g_ug[b*NM + i] + vgj) + 0.4f*S;
      } else v = -1e30f;
    }
    ev[t] = v;
  }
  float m = -3.4e38f;
  #pragma unroll
  for (int t = 0; t < 5; t++) m = fmaxf(m, ev[t]);
  #pragma unroll
  for (int s = 16; s; s >>= 1) m = fmaxf(m, __shfl_xor_sync(0xffffffffu, m, s));
  float sum = 0.f;
  #pragma unroll
  for (int t = 0; t < 5; t++) { ev[t] = (ev[t] > -3.0e38f) ? expf(ev[t] - m) : 0.f; sum += ev[t]; }
  #pragma unroll
  for (int s = 16; s; s >>= 1) sum += __shfl_xor_sync(0xffffffffu, sum, s);
  float inv = 1.0f / sum;
  float* aT = g_alphaT + (b*NM + j)*NMP;
  #pragma unroll
  for (int t = 0; t < 5; t++) {
    int i = lane + 32*t;
    if (i < NM) aT[i] = ev[t] * inv;
    else if (i < NMP) aT[i] = 0.f;
  }
}

// ---------------- K4: agg_cg, 64x64 tile, 4x4 (pure stage) ------------------
__global__ __launch_bounds__(256)
void k4_aggcg(const float* __restrict__ gat_bias) {
  __shared__ __align__(16) float ATs[16][68];
  __shared__ __align__(16) float Xs[16][68];
  int b = blockIdx.z;
  int j0 = blockIdx.x * 64, l0 = blockIdx.y * 64;
  int tid = threadIdx.x;
  int ty = tid >> 4, tx = tid & 15;
  int rr = tid >> 2, g = tid & 3;
  const float* aT = g_alphaT + b*NM*NMP;
  const float* xl = g_xl_cg + b*NM*NL;
  float acc[4][4] = {};
  for (int step = 0; step < 9; step++) {
    int ib = step*16;
    float4 av = make_float4(0.f,0.f,0.f,0.f);
    // NOTE: rows with j==NN (or j>=NM) read whatever is in alphaT; their
    // outputs land in dead agg rows, never read downstream.
    if (j0 + rr < NM) av = *(const float4*)&aT[(j0 + rr)*NMP + ib + g*4];
    int fi = tid >> 4, c4 = (tid & 15) * 4;
    float4 xv = make_float4(0.f,0.f,0.f,0.f);
    if (l0 + c4 < NL) xv = *(const float4*)&xl[(ib + fi)*NL + l0 + c4];
    __syncthreads();
    int kb = g*4;
    ATs[kb+0][rr] = av.x; ATs[kb+1][rr] = av.y; ATs[kb+2][rr] = av.z; ATs[kb+3][rr] = av.w;
    *(float4*)&Xs[fi][c4] = xv;
    __syncthreads();
    #pragma unroll
    for (int k = 0; k < 16; k++) {
      float4 a4 = *(const float4*)&ATs[k][4*ty];
      float4 x4 = *(const float4*)&Xs[k][4*tx];
      float avv[4] = {a4.x, a4.y, a4.z, a4.w};
      float xvv[4] = {x4.x, x4.y, x4.z, x4.w};
      #pragma unroll
      for (int di = 0; di < 4; di++)
        #pragma unroll
        for (int dj = 0; dj < 4; dj++)
          acc[di][dj] = fmaf(avv[di], xvv[dj], acc[di][dj]);
    }
  }
  {
    float a144[4], x144[4];
    #pragma unroll
    for (int di = 0; di < 4; di++) {
      int j = j0 + 4*ty + di;
      a144[di] = (j < NM) ? aT[j*NMP + 144] : 0.f;
    }
    #pragma unroll
    for (int dj = 0; dj < 4; dj++) {
      int l = l0 + 4*tx + dj;
      x144[dj] = (l < NL) ? xl[144*NL + l] : 0.f;
    }
    #pragma unroll
    for (int di = 0; di < 4; di++)
      #pragma unroll
      for (int dj = 0; dj < 4; dj++)
        acc[di][dj] = fmaf(a144[di], x144[dj], acc[di][dj]);
  }
  float* outp = g_agg_cg + b*NM*NL;
  #pragma unroll
  for (int di = 0; di < 4; di++) {
    int j = j0 + 4*ty + di;
    if (j < NM) {
      #pragma unroll
      for (int dj = 0; dj < 4; dj++) {
        int l = l0 + 4*tx + dj;
        if (l < NL) outp[j*NL + l] = fmaxf(acc[di][dj] + gat_bias[l], 0.f);
      }
    }
  }
}

// ---------------- K6: dual projection: id->loss2, cg->d_out, scalar ---------
__global__ void k6_out(const float* __restrict__ out_w,
                       const float* __restrict__ out_b,
                       const float* __restrict__ latent,
                       float* __restrict__ d_out) {
  __shared__ __align__(16) float sm[2*32*34 + 256];
  float (*As2)[34] = (float(*)[34])sm;
  float (*Ws)[34]  = (float(*)[34])(sm + 32*34);
  float* red = sm + 2*32*34;
  int bid = blockIdx.x;
  int mode = bid / 20;            // 0 = id (loss2), 1 = cg (write out)
  int q = bid % 20;
  int r0 = (q / 2) * 32, c0 = (q % 2) * 32;
  const float* A = mode ? g_agg_cg : g_agg_id;
  int tid = threadIdx.x, ty = tid >> 4, tx = tid & 15;
  float a00 = 0.f, a01 = 0.f, a10 = 0.f, a11 = 0.f;
  for (int k0 = 0; k0 < NL; k0 += 32) {
    for (int idx = tid; idx < 1024; idx += 256) {
      int r = idx >> 5, c = idx & 31;
      As2[c][r] = (r0 + r < NB*NM) ? A[(r0 + r)*NL + k0 + c] : 0.f;
      Ws[r][c]  = out_w[(k0 + r)*NC + c0 + c];
    }
    __syncthreads();
    #pragma unroll
    for (int k = 0; k < 32; k++) {
      float2 ar = *(const float2*)&As2[k][2*ty];
      float2 w  = *(const float2*)&Ws[k][2*tx];
      a00 = fmaf(ar.x, w.x, a00); a01 = fmaf(ar.x, w.y, a01);
      a10 = fmaf(ar.y, w.x, a10); a11 = fmaf(ar.y, w.y, a11);
    }
    __syncthreads();
  }
  float y[2][2] = {{a00 + out_b[c0 + 2*tx], a01 + out_b[c0 + 2*tx + 1]},
                   {a10 + out_b[c0 + 2*tx], a11 + out_b[c0 + 2*tx + 1]}};
  float lp = 0.f;
  #pragma unroll
  for (int di = 0; di < 2; di++) {
    int r = r0 + 2*ty + di;
    if (r < NB*NM) {
      int b = r / NM, n = r % NM;
      if (n < NN) {
        #pragma unroll
        for (int dj = 0; dj < 2; dj++) {
          int c = c0 + 2*tx + dj;
          int oidx = (b*NC + c)*NN + n;
          if (mode == 1) d_out[oidx] = y[di][dj];
          else { float d = latent[oidx] - y[di][dj]; lp += d*d; }
        }
      }
    }
  }
  if (mode == 0) {
    red[tid] = lp; __syncthreads();
    for (int s = 128; s; s >>= 1) { if (tid < s) red[tid] += red[tid + s]; __syncthreads(); }
    if (tid == 0) atomicAdd(&g_loss2, red[0]);
    __syncthreads();
  }
  if (tid == 0) {
    __threadfence();
    unsigned int old = atomicAdd(&g_cnt6, 1u);
    if (old == gridDim.x - 1) {
      float L2 = atomicAdd(&g_loss2, 0.f);
      float L1 = atomicAdd(&g_loss1, 0.f);
      d_out[NB*NN*NC] = L1 / (float)(NB*NN*NN) + L2 / (float)(NB*NN*NC);
    }
  }
}

// ---------------- launch ----------------------------------------------------
extern "C" void kernel_launch(void* const* d_in, const int* in_sizes, int n_in,
                              void* d_out, int out_size) {
  (void)in_sizes; (void)n_in; (void)out_size;
  const float* latent    = (const float*)d_in[0];
  const float* a_dense_b = (const float*)d_in[2];
  const float* disc_w1   = (const float*)d_in[3];
  const float* disc_b1   = (const float*)d_in[4];
  const float* disc_w2   = (const float*)d_in[5];
  const float* disc_b2   = (const float*)d_in[6];
  const float* gat_wl    = (const float*)d_in[7];
  const float* gat_bl    = (const float*)d_in[8];
  const float* gat_wr    = (const float*)d_in[9];
  const float* gat_br    = (const float*)d_in[10];
  const float* gat_att   = (const float*)d_in[11];
  const float* gat_bias  = (const float*)d_in[12];
  const float* out_w     = (const float*)d_in[13];
  const float* out_b     = (const float*)d_in[14];
  float* out = (float*)d_out;

  uint32_t kg0, kg1, n10, n11, n20, n21, a, b;
  tf2x32(0u, 42u, 0u, 0u, a, b); kg0 = a; kg1 = b;
  tf2x32(0u, 42u, 0u, 1u, a, b); n10 = a; n11 = b;
  tf2x32(0u, 42u, 0u, 2u, a, b); n20 = a; n21 = b;

  int k0_threads = NB*NN*NC + NL + 2*NB*NM*NC + 2*NB*NN + 2*NB*NM;
  k0_prep<<<(k0_threads + 255)/256, 256>>>(latent, a_dense_b, disc_w1, disc_b1,
                                           n10, n11, n20, n21);
  k1_gemm64<<<dim3(5, 13, 6), 256>>>(disc_w1, gat_wl, gat_wr, gat_bl, gat_br,
                                     disc_w2, gat_att);
  k235_mega<<<360 + NB*NN, 256>>>(disc_w2, gat_att, gat_bias);
  k2b_decide<<<162, 256>>>(disc_b2, kg0, kg1);
  k35_softmax<<<37, 256>>>();
  k4_aggcg<<<dim3(3, 13, 2), 256>>>(gat_bias);
  k6_out<<<40, 256>>>(out_w, out_b, latent, out);
}